// round 2
// baseline (speedup 1.0000x reference)
#include <cuda_runtime.h>
#include <math.h>

// ---------------- problem constants ----------------
#define B_  4
#define S_  1024
#define D_  1024
#define E_  4
#define H_  2816           // HID
#define BS_ (B_*S_)        // 4096 tokens
#define CAP BS_            // worst-case tokens per expert
#define ADA6 (6*D_)        // 6144
#define BSD ((long)BS_*D_) // 4194304

// ---------------- device scratch (static, allocation-free) ----------------
__device__ float g_silu[B_*D_];
__device__ float g_ada [B_*ADA6];
__device__ float g_h   [BS_*D_];
__device__ float g_q   [BS_*D_];
__device__ float g_k   [BS_*D_];
__device__ float g_v   [BS_*D_];
__device__ float g_sc  [(long)B_*D_*D_];
__device__ float g_ao  [BS_*D_];
__device__ float g_x1  [BS_*D_];
__device__ float g_h2  [BS_*D_];
__device__ float g_lg  [BS_*E_];
__device__ float g_pr  [BS_*E_];
__device__ int   g_cnt [E_];
__device__ int   g_list[E_*CAP];
__device__ int   g_te  [BS_*2];
__device__ int   g_tp  [BS_*2];
__device__ float g_tw  [BS_*2];
__device__ float g_buf1[(long)E_*CAP*H_];   // h1 then sin(h1)*h3
__device__ float g_ebuf[(long)E_*CAP*D_];   // per-slot expert outputs

// ---------------- generic 128x128x8 fp32 GEMM ----------------
// MODE 0: C[M,N] = A[M,K] * B[K,N]           (A row-major lda=K, B row-major ldb=N)
// MODE 1: C[M,N] = A^T * B, A stored [K,M]   (lda=M), B [K,N]
// MODE 2: C[M,N] = A * B^T, B stored [N,K]   (ldb=K)
// EPI  0: store acc
// EPI  1: C = resid + gate[b,:]*acc   (b = row/S, gate row stride gateStride)
// EPI  2: C = sin(C_old) * acc        (C_old read from C itself)
template<int MODE, int EPI, bool GATHER>
__global__ void __launch_bounds__(256, 2) gemm_kernel(
    const float* __restrict__ A, const float* __restrict__ Bm, float* __restrict__ C,
    int M, int N, int K,
    long aStride, long bStride, long cStride,
    const int* __restrict__ gatherIdx, int gatherCap,
    const int* __restrict__ counts,
    const float* __restrict__ resid, const float* __restrict__ gate,
    int gateStride, int S)
{
    __shared__ float As[8][128];
    __shared__ float Bs[8][128];

    const int z  = blockIdx.z;
    const int m0 = blockIdx.x * 128;
    const int n0 = blockIdx.y * 128;
    const int Meff = counts ? counts[z] : M;
    if (m0 >= Meff) return;

    A += (long)z * aStride;
    Bm += (long)z * bStride;
    C += (long)z * cStride;

    const int tid = threadIdx.x;
    const int ar  = tid >> 1;          // 0..127
    const int ak  = (tid & 1) << 2;    // 0 or 4
    const int bkr = tid >> 5;          // 0..7
    const int bc  = (tid & 31) << 2;   // 0..124

    // A source
    const float* aSrc;
    bool aValid = true;
    if (MODE == 1) {
        aSrc = A + (long)bkr * M + m0 + bc;
    } else {
        int row = m0 + ar;
        aValid = (row < Meff);
        long arow = 0;
        if (aValid) arow = GATHER ? (long)gatherIdx[(long)z * gatherCap + row] : (long)row;
        aSrc = A + arow * (long)K + ak;
    }
    // B source
    const float* bSrc;
    if (MODE == 2) bSrc = Bm + (long)(n0 + ar) * K + ak;
    else           bSrc = Bm + (long)bkr * N + n0 + bc;

    float acc[8][8];
#pragma unroll
    for (int i = 0; i < 8; i++)
#pragma unroll
        for (int j = 0; j < 8; j++) acc[i][j] = 0.f;

    const int ty8 = (tid >> 4) << 3;
    const int tx8 = (tid & 15) << 3;

    for (int k0 = 0; k0 < K; k0 += 8) {
        if (MODE == 1) {
            float4 va = *(const float4*)(aSrc + (long)k0 * M);
            *(float4*)&As[bkr][bc] = va;
        } else {
            float4 va = make_float4(0.f, 0.f, 0.f, 0.f);
            if (aValid) va = *(const float4*)(aSrc + k0);
            As[ak + 0][ar] = va.x; As[ak + 1][ar] = va.y;
            As[ak + 2][ar] = va.z; As[ak + 3][ar] = va.w;
        }
        if (MODE == 2) {
            float4 vb = *(const float4*)(bSrc + k0);
            Bs[ak + 0][ar] = vb.x; Bs[ak + 1][ar] = vb.y;
            Bs[ak + 2][ar] = vb.z; Bs[ak + 3][ar] = vb.w;
        } else {
            float4 vb = *(const float4*)(bSrc + (long)k0 * N);
            *(float4*)&Bs[bkr][bc] = vb;
        }
        __syncthreads();
#pragma unroll
        for (int kk = 0; kk < 8; kk++) {
            float a[8], b[8];
            *(float4*)&a[0] = *(const float4*)&As[kk][ty8];
            *(float4*)&a[4] = *(const float4*)&As[kk][ty8 + 4];
            *(float4*)&b[0] = *(const float4*)&Bs[kk][tx8];
            *(float4*)&b[4] = *(const float4*)&Bs[kk][tx8 + 4];
#pragma unroll
            for (int i = 0; i < 8; i++)
#pragma unroll
                for (int j = 0; j < 8; j++)
                    acc[i][j] = fmaf(a[i], b[j], acc[i][j]);
        }
        __syncthreads();
    }

    // epilogue
#pragma unroll
    for (int i = 0; i < 8; i++) {
        int r = m0 + ty8 + i;
        if (r >= Meff) break;
        long off = (long)r * N + n0 + tx8;
#pragma unroll
        for (int jj = 0; jj < 8; jj += 4) {
            float4 o;
            o.x = acc[i][jj + 0]; o.y = acc[i][jj + 1];
            o.z = acc[i][jj + 2]; o.w = acc[i][jj + 3];
            if (EPI == 1) {
                int bb = r / S;
                float4 rv = *(const float4*)&resid[off + jj];
                float4 gv = *(const float4*)&gate[(long)bb * gateStride + n0 + tx8 + jj];
                o.x = rv.x + gv.x * o.x; o.y = rv.y + gv.y * o.y;
                o.z = rv.z + gv.z * o.z; o.w = rv.w + gv.w * o.w;
            } else if (EPI == 2) {
                float4 old = *(const float4*)&C[off + jj];
                o.x = sinf(old.x) * o.x; o.y = sinf(old.y) * o.y;
                o.z = sinf(old.z) * o.z; o.w = sinf(old.w) * o.w;
            }
            *(float4*)&C[off + jj] = o;
        }
    }
}

// ---------------- small kernels ----------------
__global__ void silu_kernel(const float* __restrict__ in, float* __restrict__ o) {
    int i = blockIdx.x * 256 + threadIdx.x;
    if (i < B_ * D_) { float v = in[i]; o[i] = v / (1.f + expf(-v)); }
}

// ada = silu(adaln) @ ada_w + ada_b    [B,6D], 128 threads/block, 48 blocks
__global__ void __launch_bounds__(128) ada_kernel(const float* __restrict__ sl,
                                                  const float* __restrict__ W,
                                                  const float* __restrict__ bias,
                                                  float* __restrict__ ada) {
    __shared__ float s[B_ * D_];
    int col = blockIdx.x * 128 + threadIdx.x;
    for (int i = threadIdx.x; i < B_ * D_; i += 128) s[i] = sl[i];
    __syncthreads();
    float a0 = 0.f, a1 = 0.f, a2 = 0.f, a3 = 0.f;
    for (int k = 0; k < D_; k++) {
        float w = W[(long)k * ADA6 + col];
        a0 = fmaf(s[k], w, a0);
        a1 = fmaf(s[D_ + k], w, a1);
        a2 = fmaf(s[2 * D_ + k], w, a2);
        a3 = fmaf(s[3 * D_ + k], w, a3);
    }
    float bv = bias[col];
    ada[col] = a0 + bv;
    ada[ADA6 + col] = a1 + bv;
    ada[2L * ADA6 + col] = a2 + bv;
    ada[3L * ADA6 + col] = a3 + bv;
}

// LayerNorm over last dim (=1024), optional adaLN modulation
__global__ void __launch_bounds__(256) ln_kernel(const float* __restrict__ in, float* __restrict__ out,
    const float* __restrict__ w, const float* __restrict__ b,
    const float* __restrict__ scale, const float* __restrict__ shift,
    int adaStride, int S, float eps)
{
    long row = blockIdx.x;
    const float* xr = in + row * D_;
    int t = threadIdx.x;
    float4 v = *(const float4*)&xr[t * 4];
    float s1 = v.x + v.y + v.z + v.w;
    float s2 = v.x * v.x + v.y * v.y + v.z * v.z + v.w * v.w;
    __shared__ float sm[16];
#pragma unroll
    for (int o = 16; o; o >>= 1) {
        s1 += __shfl_down_sync(0xffffffffu, s1, o);
        s2 += __shfl_down_sync(0xffffffffu, s2, o);
    }
    if ((t & 31) == 0) { sm[t >> 5] = s1; sm[8 + (t >> 5)] = s2; }
    __syncthreads();
    if (t == 0) {
        float a = 0.f, c = 0.f;
        for (int i = 0; i < 8; i++) { a += sm[i]; c += sm[8 + i]; }
        sm[0] = a; sm[8] = c;
    }
    __syncthreads();
    float mean = sm[0] * (1.f / D_);
    float var = sm[8] * (1.f / D_) - mean * mean;
    float rs = rsqrtf(var + eps);
    int c0 = t * 4;
    float4 wv = *(const float4*)&w[c0];
    float4 bv = *(const float4*)&b[c0];
    float4 o;
    o.x = (v.x - mean) * rs * wv.x + bv.x;
    o.y = (v.y - mean) * rs * wv.y + bv.y;
    o.z = (v.z - mean) * rs * wv.z + bv.z;
    o.w = (v.w - mean) * rs * wv.w + bv.w;
    if (scale) {
        int bb = (int)(row / S);
        float4 sv = *(const float4*)&scale[(long)bb * adaStride + c0];
        float4 hv = *(const float4*)&shift[(long)bb * adaStride + c0];
        o.x = o.x * (1.f + sv.x) + hv.x;
        o.y = o.y * (1.f + sv.y) + hv.y;
        o.z = o.z * (1.f + sv.z) + hv.z;
        o.w = o.w * (1.f + sv.w) + hv.w;
    }
    *(float4*)&out[row * D_ + c0] = o;
}

// row softmax, width 1024, in place
__global__ void __launch_bounds__(256) softmax_kernel(float* __restrict__ p) {
    long row = blockIdx.x;
    float* r = p + row * D_;
    int t = threadIdx.x;
    float4 v = *(const float4*)&r[t * 4];
    float m = fmaxf(fmaxf(v.x, v.y), fmaxf(v.z, v.w));
    __shared__ float sm[8];
#pragma unroll
    for (int o = 16; o; o >>= 1) m = fmaxf(m, __shfl_down_sync(0xffffffffu, m, o));
    if ((t & 31) == 0) sm[t >> 5] = m;
    __syncthreads();
    if (t == 0) { float a = sm[0]; for (int i = 1; i < 8; i++) a = fmaxf(a, sm[i]); sm[0] = a; }
    __syncthreads();
    m = sm[0];
    float e0 = expf(v.x - m), e1 = expf(v.y - m), e2 = expf(v.z - m), e3 = expf(v.w - m);
    float s = e0 + e1 + e2 + e3;
    __syncthreads();
#pragma unroll
    for (int o = 16; o; o >>= 1) s += __shfl_down_sync(0xffffffffu, s, o);
    if ((t & 31) == 0) sm[t >> 5] = s;
    __syncthreads();
    if (t == 0) { float a = 0.f; for (int i = 0; i < 8; i++) a += sm[i]; sm[0] = a; }
    __syncthreads();
    float inv = 1.f / sm[0];
    *(float4*)&r[t * 4] = make_float4(e0 * inv, e1 * inv, e2 * inv, e3 * inv);
}

// router logits: one block per token, 4 outputs
__global__ void __launch_bounds__(256) router_kernel(const float* __restrict__ h,
    const float* __restrict__ rw, const float* __restrict__ rb, float* __restrict__ lg)
{
    int tok = blockIdx.x;
    const float* hr = h + (long)tok * D_;
    int t = threadIdx.x;
    float4 hv = *(const float4*)&hr[t * 4];
    float hvv[4] = { hv.x, hv.y, hv.z, hv.w };
    float a0 = 0.f, a1 = 0.f, a2 = 0.f, a3 = 0.f;
#pragma unroll
    for (int j = 0; j < 4; j++) {
        int k = t * 4 + j;
        float4 w = *(const float4*)&rw[(long)k * 4];
        float xv = hvv[j];
        a0 = fmaf(xv, w.x, a0); a1 = fmaf(xv, w.y, a1);
        a2 = fmaf(xv, w.z, a2); a3 = fmaf(xv, w.w, a3);
    }
#pragma unroll
    for (int o = 16; o; o >>= 1) {
        a0 += __shfl_down_sync(0xffffffffu, a0, o);
        a1 += __shfl_down_sync(0xffffffffu, a1, o);
        a2 += __shfl_down_sync(0xffffffffu, a2, o);
        a3 += __shfl_down_sync(0xffffffffu, a3, o);
    }
    __shared__ float sm[8][4];
    if ((t & 31) == 0) { int w5 = t >> 5; sm[w5][0] = a0; sm[w5][1] = a1; sm[w5][2] = a2; sm[w5][3] = a3; }
    __syncthreads();
    if (t < 4) {
        float s = 0.f;
        for (int i = 0; i < 8; i++) s += sm[i][t];
        lg[(long)tok * 4 + t] = s + rb[t];
    }
}

// L2-normalize logits along SEQUENCE dim (faithful quirk). block per (b,e)
__global__ void __launch_bounds__(256) seqnorm_kernel(float* __restrict__ lg) {
    int b = blockIdx.x >> 2, e = blockIdx.x & 3;
    int t = threadIdx.x;
    float s = 0.f;
    for (int i = t; i < S_; i += 256) {
        float v = lg[((long)(b * S_ + i)) * 4 + e];
        s += v * v;
    }
    __shared__ float sm[8];
#pragma unroll
    for (int o = 16; o; o >>= 1) s += __shfl_down_sync(0xffffffffu, s, o);
    if ((t & 31) == 0) sm[t >> 5] = s;
    __syncthreads();
    if (t == 0) {
        float a = 0.f;
        for (int i = 0; i < 8; i++) a += sm[i];
        sm[0] = 1.f / fmaxf(sqrtf(a), 1e-12f);
    }
    __syncthreads();
    float sc = sm[0];
    for (int i = t; i < S_; i += 256) lg[((long)(b * S_ + i)) * 4 + e] *= sc;
}

__global__ void zero_kernel(int* cnt) { if (threadIdx.x < E_) cnt[threadIdx.x] = 0; }

// softmax over E, top-2, build expert dispatch lists + per-token slot meta
__global__ void topk_kernel(const float* __restrict__ lg, float* __restrict__ pr,
    int* __restrict__ cnt, int* __restrict__ list,
    int* __restrict__ te, int* __restrict__ tp, float* __restrict__ tw)
{
    int tok = blockIdx.x * 256 + threadIdx.x;
    if (tok >= BS_) return;
    float l[4];
#pragma unroll
    for (int e = 0; e < 4; e++) l[e] = lg[(long)tok * 4 + e];
    float m = fmaxf(fmaxf(l[0], l[1]), fmaxf(l[2], l[3]));
    float p[4]; float s = 0.f;
#pragma unroll
    for (int e = 0; e < 4; e++) { p[e] = expf(l[e] - m); s += p[e]; }
    float inv = 1.f / s;
#pragma unroll
    for (int e = 0; e < 4; e++) { p[e] *= inv; pr[(long)tok * 4 + e] = p[e]; }
    int a0 = 0;
#pragma unroll
    for (int e = 1; e < 4; e++) if (p[e] > p[a0]) a0 = e;
    int a1 = -1; float pb = -1.f;
#pragma unroll
    for (int e = 0; e < 4; e++) if (e != a0 && p[e] > pb) { pb = p[e]; a1 = e; }
    int s0 = atomicAdd(&cnt[a0], 1); list[a0 * CAP + s0] = tok;
    int s1 = atomicAdd(&cnt[a1], 1); list[a1 * CAP + s1] = tok;
    te[2 * tok] = a0;     tp[2 * tok] = s0;     tw[2 * tok] = p[a0];
    te[2 * tok + 1] = a1; tp[2 * tok + 1] = s1; tw[2 * tok + 1] = p[a1];
}

// out[tok,d] = w0*ebuf[e0][p0][d] + w1*ebuf[e1][p1][d]   (deterministic per-token gather)
__global__ void combine_kernel(const float* __restrict__ ebuf,
    const int* __restrict__ te, const int* __restrict__ tp,
    const float* __restrict__ tw, float* __restrict__ out)
{
    long gid = (long)blockIdx.x * 256 + threadIdx.x;
    int tok = (int)(gid >> 10);
    int d = (int)(gid & 1023);
    int e0 = te[2 * tok], e1 = te[2 * tok + 1];
    long r0 = ((long)e0 * CAP + tp[2 * tok]) * D_ + d;
    long r1 = ((long)e1 * CAP + tp[2 * tok + 1]) * D_ + d;
    out[gid] = tw[2 * tok] * ebuf[r0] + tw[2 * tok + 1] * ebuf[r1];
}

// aux = sum_{s,e} (1/E - mean_b probs)^2 ; write to out[BSD..out_size)
__global__ void __launch_bounds__(256) aux_kernel(const float* __restrict__ pr,
                                                  float* __restrict__ out, long out_size)
{
    int t = threadIdx.x;
    float acc = 0.f;
    for (int i = t; i < S_ * E_; i += 256) {
        int s = i >> 2, e = i & 3;
        float av = 0.f;
#pragma unroll
        for (int b = 0; b < B_; b++) av += pr[((long)(b * S_ + s)) * 4 + e];
        av *= 0.25f;
        float d = 0.25f - av;
        acc += d * d;
    }
    __shared__ float sm[8];
#pragma unroll
    for (int o = 16; o; o >>= 1) acc += __shfl_down_sync(0xffffffffu, acc, o);
    if ((t & 31) == 0) sm[t >> 5] = acc;
    __syncthreads();
    if (t == 0) {
        float a = 0.f;
        for (int i = 0; i < 8; i++) a += sm[i];
        for (long i = BSD; i < out_size; i++) out[i] = a;
    }
}

// ---------------- host launcher ----------------
extern "C" void kernel_launch(void* const* d_in, const int* in_sizes, int n_in,
                              void* d_out, int out_size)
{
    (void)in_sizes; (void)n_in;
    const float* x     = (const float*)d_in[0];
    const float* adaln = (const float*)d_in[2];
    const float* wq    = (const float*)d_in[3];
    const float* wk    = (const float*)d_in[4];
    const float* wv    = (const float*)d_in[5];
    const float* wo    = (const float*)d_in[6];
    const float* qnw   = (const float*)d_in[7];
    const float* qnb   = (const float*)d_in[8];
    const float* knw   = (const float*)d_in[9];
    const float* knb   = (const float*)d_in[10];
    const float* anw   = (const float*)d_in[11];
    const float* anb   = (const float*)d_in[12];
    const float* w1    = (const float*)d_in[15];
    const float* w2    = (const float*)d_in[16];
    const float* w3    = (const float*)d_in[17];
    const float* rw    = (const float*)d_in[18];
    const float* rb    = (const float*)d_in[19];
    const float* adaw  = (const float*)d_in[20];
    const float* adab  = (const float*)d_in[21];
    const float* fnw   = (const float*)d_in[13];
    const float* fnb   = (const float*)d_in[14];
    float* out = (float*)d_out;

    float *silu_, *ada_, *h_, *q_, *k_, *v_, *sc_, *ao_, *x1_, *h2_, *lg_, *pr_, *buf1_, *ebuf_, *tw_;
    int *cnt_, *list_, *te_, *tp_;
    cudaGetSymbolAddress((void**)&silu_, g_silu);
    cudaGetSymbolAddress((void**)&ada_,  g_ada);
    cudaGetSymbolAddress((void**)&h_,    g_h);
    cudaGetSymbolAddress((void**)&q_,    g_q);
    cudaGetSymbolAddress((void**)&k_,    g_k);
    cudaGetSymbolAddress((void**)&v_,    g_v);
    cudaGetSymbolAddress((void**)&sc_,   g_sc);
    cudaGetSymbolAddress((void**)&ao_,   g_ao);
    cudaGetSymbolAddress((void**)&x1_,   g_x1);
    cudaGetSymbolAddress((void**)&h2_,   g_h2);
    cudaGetSymbolAddress((void**)&lg_,   g_lg);
    cudaGetSymbolAddress((void**)&pr_,   g_pr);
    cudaGetSymbolAddress((void**)&buf1_, g_buf1);
    cudaGetSymbolAddress((void**)&ebuf_, g_ebuf);
    cudaGetSymbolAddress((void**)&tw_,   g_tw);
    cudaGetSymbolAddress((void**)&cnt_,  g_cnt);
    cudaGetSymbolAddress((void**)&list_, g_list);
    cudaGetSymbolAddress((void**)&te_,   g_te);
    cudaGetSymbolAddress((void**)&tp_,   g_tp);

    const float eps = 1e-5f;
    const long SD = (long)S_ * D_;
    const long DDl = (long)D_ * D_;

    // 1. adaLN modulation vectors
    silu_kernel<<<(B_*D_ + 255) / 256, 256>>>(adaln, silu_);
    ada_kernel<<<ADA6 / 128, 128>>>(silu_, adaw, adab, ada_);

    // 2. h = modulate(LN(x), msa)
    ln_kernel<<<BS_, 256>>>(x, h_, anw, anb, ada_ + D_, ada_, ADA6, S_, eps);

    // 3. q,k,v GEMMs
    gemm_kernel<0,0,false><<<dim3(32, 8, 1), 256>>>(h_, wq, q_, BS_, D_, D_, 0,0,0,
        nullptr,0,nullptr, nullptr,nullptr,0,0);
    gemm_kernel<0,0,false><<<dim3(32, 8, 1), 256>>>(h_, wk, k_, BS_, D_, D_, 0,0,0,
        nullptr,0,nullptr, nullptr,nullptr,0,0);
    gemm_kernel<0,0,false><<<dim3(32, 8, 1), 256>>>(h_, wv, v_, BS_, D_, D_, 0,0,0,
        nullptr,0,nullptr, nullptr,nullptr,0,0);

    // 4. q_norm / k_norm (in place)
    ln_kernel<<<BS_, 256>>>(q_, q_, qnw, qnb, nullptr, nullptr, 0, S_, eps);
    ln_kernel<<<BS_, 256>>>(k_, k_, knw, knb, nullptr, nullptr, 0, S_, eps);

    // 5. scores[b] = q[b]^T @ k[b]   (feature-dim attention, [B,D,D])
    gemm_kernel<1,0,false><<<dim3(8, 8, B_), 256>>>(q_, k_, sc_, D_, D_, S_,
        SD, SD, DDl, nullptr,0,nullptr, nullptr,nullptr,0,0);

    // 6. softmax over last dim
    softmax_kernel<<<B_ * D_, 256>>>(sc_);

    // 7. attn_out[b] = v[b] @ attn[b]^T
    gemm_kernel<2,0,false><<<dim3(8, 8, B_), 256>>>(v_, sc_, ao_, S_, D_, D_,
        SD, DDl, SD, nullptr,0,nullptr, nullptr,nullptr,0,0);

    // 8. x1 = x + gate_msa * (attn_out @ wo)
    gemm_kernel<0,1,false><<<dim3(32, 8, 1), 256>>>(ao_, wo, x1_, BS_, D_, D_, 0,0,0,
        nullptr,0,nullptr, x, ada_ + 2L*D_, ADA6, S_);

    // 9. h2 = modulate(LN(x1), mlp)
    ln_kernel<<<BS_, 256>>>(x1_, h2_, fnw, fnb, ada_ + 4L*D_, ada_ + 3L*D_, ADA6, S_, eps);

    // 10. router + seq-dim L2 norm + softmax/top2 dispatch
    router_kernel<<<BS_, 256>>>(h2_, rw, rb, lg_);
    seqnorm_kernel<<<B_ * E_, 256>>>(lg_);
    zero_kernel<<<1, 32>>>(cnt_);
    topk_kernel<<<BS_ / 256, 256>>>(lg_, pr_, cnt_, list_, te_, tp_, tw_);

    // 11. expert up-projections (gathered rows), gated = sin(h1) * h3
    gemm_kernel<0,0,true><<<dim3(CAP / 128, H_ / 128, E_), 256>>>(h2_, w1, buf1_,
        CAP, H_, D_, 0, (long)D_ * H_, (long)CAP * H_, list_, CAP, cnt_,
        nullptr, nullptr, 0, 0);
    gemm_kernel<0,2,true><<<dim3(CAP / 128, H_ / 128, E_), 256>>>(h2_, w3, buf1_,
        CAP, H_, D_, 0, (long)D_ * H_, (long)CAP * H_, list_, CAP, cnt_,
        nullptr, nullptr, 0, 0);

    // 12. expert down-projection
    gemm_kernel<0,0,false><<<dim3(CAP / 128, D_ / 128, E_), 256>>>(buf1_, w2, ebuf_,
        CAP, D_, H_, (long)CAP * H_, (long)H_ * D_, (long)CAP * D_,
        nullptr, 0, cnt_, nullptr, nullptr, 0, 0);

    // 13. per-token combine -> d_out, then aux scalar
    combine_kernel<<<(int)(BSD / 256), 256>>>(ebuf_, te_, tp_, tw_, out);
    aux_kernel<<<1, 256>>>(pr_, out, (long)out_size);
}

// round 4
// speedup vs baseline: 2.5775x; 2.5775x over previous
#include <cuda_runtime.h>
#include <cuda_bf16.h>
#include <math.h>

typedef unsigned int u32;
typedef __nv_bfloat16 bf;

#define B_  4
#define S_  1024
#define D_  1024
#define E_  4
#define H_  2816
#define BS_ (B_*S_)
#define CAP BS_
#define ADA6 (6*D_)
#define BSD ((long)BS_*D_)
#define K3D 3072
#define K3S 3072
#define K3H 8448
#define STAGE 32768
#define SMEMSZ (3*STAGE)

// ---------------- device scratch ----------------
__device__ __align__(16) float g_silu[B_*D_];
__device__ __align__(16) float g_ada [B_*ADA6];
__device__ __align__(16) bf    g_hs  [(long)BS_*K3D];
__device__ __align__(16) bf    g_wqT [(long)D_*K3D];
__device__ __align__(16) bf    g_wkT [(long)D_*K3D];
__device__ __align__(16) bf    g_wvT [(long)D_*K3D];
__device__ __align__(16) bf    g_woT [(long)D_*K3D];
__device__ __align__(16) float g_q   [BS_*D_];
__device__ __align__(16) float g_k   [BS_*D_];
__device__ __align__(16) bf    g_qT  [(long)B_*D_*K3S];
__device__ __align__(16) bf    g_kT  [(long)B_*D_*K3S];
__device__ __align__(16) bf    g_vs  [(long)BS_*K3D];
__device__ __align__(16) float g_sc  [(long)B_*D_*D_];
__device__ __align__(16) bf    g_at  [(long)B_*D_*K3D];
__device__ __align__(16) bf    g_aos [(long)BS_*K3D];
__device__ __align__(16) float g_x1  [BS_*D_];
__device__ __align__(16) float g_h2  [BS_*D_];
__device__ __align__(16) bf    g_h2s [(long)BS_*K3D];
__device__ __align__(16) bf    g_w1T [(long)E_*H_*K3D];
__device__ __align__(16) bf    g_w3T [(long)E_*H_*K3D];
__device__ __align__(16) bf    g_w2T [(long)E_*D_*K3H];
__device__ __align__(16) float g_buf1[(long)E_*CAP*H_];
__device__ __align__(16) bf    g_gs  [(long)E_*CAP*K3H];
__device__ __align__(16) float g_ebuf[(long)E_*CAP*D_];
__device__ __align__(16) float g_lg  [BS_*E_];
__device__ __align__(16) float g_pr  [BS_*E_];
__device__ int   g_cnt [E_];
__device__ int   g_list[E_*CAP];
__device__ int   g_te  [BS_*2];
__device__ int   g_tp  [BS_*2];
__device__ __align__(16) float g_tw  [BS_*2];

// ---------------- helpers ----------------
__device__ __forceinline__ u32 smem_u32(const void* p) {
    u32 a;
    asm("{ .reg .u64 t; cvta.to.shared.u64 t, %1; cvt.u32.u64 %0, t; }" : "=r"(a) : "l"(p));
    return a;
}
__device__ __forceinline__ u32 swz(u32 o) { return o ^ ((o >> 3) & 0x70); }
__device__ __forceinline__ void bsplit(float v, bf& h, bf& l) {
    h = __float2bfloat16(v);
    l = __float2bfloat16(v - __bfloat162float(h));
}
#define CP16(dst, src) asm volatile("cp.async.cg.shared.global [%0], [%1], 16;" :: "r"(dst), "l"(src))
#define CP_COMMIT()    asm volatile("cp.async.commit_group;")
#define CP_WAIT1()     asm volatile("cp.async.wait_group 1;")
#define LDM4(r, ad) asm volatile("ldmatrix.sync.aligned.m8n8.x4.shared.b16 {%0,%1,%2,%3}, [%4];" \
    : "=r"((r)[0]), "=r"((r)[1]), "=r"((r)[2]), "=r"((r)[3]) : "r"(ad))
#define MMA(c, a, b0, b1) asm volatile( \
    "mma.sync.aligned.m16n8k16.row.col.f32.bf16.bf16.f32 " \
    "{%0,%1,%2,%3}, {%4,%5,%6,%7}, {%8,%9}, {%0,%1,%2,%3};" \
    : "+f"((c)[0]), "+f"((c)[1]), "+f"((c)[2]), "+f"((c)[3]) \
    : "r"((a)[0]), "r"((a)[1]), "r"((a)[2]), "r"((a)[3]), "r"(b0), "r"(b1))

// ---------------- HMMA GEMM: C[M,N] = A[M,K'] * B[N,K']^T ----------------
// EPI 0: fp32 store   1: resid + gate*acc (fp32)   2: A-scheme split bf16 store
// EPI 3: sin(aux)*acc -> A-scheme split bf16 store
template<int EPI, bool GATHER>
__global__ void __launch_bounds__(256, 2) tcgemm(
    const bf* __restrict__ A, long aZ,
    const bf* __restrict__ Bm, long bZ,
    int Kp, int N, int Mcap,
    const int* __restrict__ counts, const int* __restrict__ list,
    float* __restrict__ Cf, long cZ,
    bf* __restrict__ Cs, int outW, long csZ,
    const float* __restrict__ aux, long auxZ,
    const float* __restrict__ gate, int gateStride)
{
    extern __shared__ __align__(16) char smem[];
    const int z = blockIdx.z;
    const int Meff = counts ? counts[z] : Mcap;
    const int m0 = blockIdx.x * 128;
    if (m0 >= Meff) return;
    const int n0 = blockIdx.y * 128;
    const int tid = threadIdx.x, wid = tid >> 5, lane = tid & 31;
    const int wm = wid >> 2, wn = wid & 3;
    const u32 sb = smem_u32(smem);

    const bf* Az = A + (long)z * aZ;
    const bf* Bz = Bm + (long)z * bZ;

    long arow[4];
#pragma unroll
    for (int i = 0; i < 4; i++) {
        int r = (i * 256 + tid) >> 3;
        int gm = m0 + r; if (gm > Meff - 1) gm = Meff - 1;
        arow[i] = GATHER ? (long)list[(long)z * CAP + gm] : (long)gm;
    }

    float acc[4][4][4];
#pragma unroll
    for (int a = 0; a < 4; a++)
#pragma unroll
        for (int b = 0; b < 4; b++)
#pragma unroll
            for (int c = 0; c < 4; c++) acc[a][b][c] = 0.f;

    const int NC = Kp / 64;

    auto issue = [&](int c) {
        int sp = c % 3;
        u32 dA = sb + sp * STAGE;
        u32 dB = dA + 16384;
        int k0 = c * 64;
#pragma unroll
        for (int i = 0; i < 4; i++) {
            int idx = i * 256 + tid, r = idx >> 3, ch = idx & 7;
            u32 sw = swz((u32)((r << 7) | (ch << 4)));
            CP16(dA + sw, Az + arow[i] * Kp + k0 + ch * 8);
            CP16(dB + sw, Bz + (long)(n0 + r) * Kp + k0 + ch * 8);
        }
    };

    issue(0); CP_COMMIT();
    issue(1); CP_COMMIT();

    for (int c = 0; c < NC; c++) {
        CP_WAIT1();
        __syncthreads();
        if (c + 2 < NC) issue(c + 2);
        CP_COMMIT();
        int sp = c % 3;
        u32 aB = sb + sp * STAGE, bB = aB + 16384;
#pragma unroll
        for (int s = 0; s < 4; s++) {
            int ks2 = s * 32;
            u32 afr[4][4], bfr[2][4];
#pragma unroll
            for (int mi = 0; mi < 4; mi++) {
                int row = wm * 64 + mi * 16 + (lane & 7) + ((lane >> 3) & 1) * 8;
                int kb = ks2 + (lane >> 4) * 16;
                LDM4(afr[mi], aB + swz((u32)(row * 128 + kb)));
            }
#pragma unroll
            for (int bi = 0; bi < 2; bi++) {
                int nrow = wn * 32 + bi * 16 + (lane & 7) + (lane >> 4) * 8;
                int kb = ks2 + ((lane >> 3) & 1) * 16;
                LDM4(bfr[bi], bB + swz((u32)(nrow * 128 + kb)));
            }
#pragma unroll
            for (int mi = 0; mi < 4; mi++)
#pragma unroll
                for (int ni = 0; ni < 4; ni++)
                    MMA(acc[mi][ni], afr[mi], bfr[ni >> 1][(ni & 1) * 2], bfr[ni >> 1][(ni & 1) * 2 + 1]);
        }
    }

    // epilogue
#pragma unroll
    for (int mi = 0; mi < 4; mi++) {
#pragma unroll
        for (int half = 0; half < 2; half++) {
            int row = m0 + wm * 64 + mi * 16 + (lane >> 2) + half * 8;
            if (row >= Meff) continue;
#pragma unroll
            for (int ni = 0; ni < 4; ni++) {
                int col = n0 + wn * 32 + ni * 8 + (lane & 3) * 2;
                float v0 = acc[mi][ni][half * 2], v1 = acc[mi][ni][half * 2 + 1];
                if (EPI == 0) {
                    float2* dst = (float2*)(Cf + (long)z * cZ + (long)row * N + col);
                    *dst = make_float2(v0, v1);
                } else if (EPI == 1) {
                    int bb = row >> 10;
                    const float2 rs = *(const float2*)(aux + (long)row * N + col);
                    const float* gv = gate + (long)bb * gateStride + col;
                    float2* dst = (float2*)(Cf + (long)row * N + col);
                    *dst = make_float2(rs.x + gv[0] * v0, rs.y + gv[1] * v1);
                } else {
                    if (EPI == 3) {
                        const float2 av = *(const float2*)(aux + (long)z * auxZ + (long)row * N + col);
                        v0 = sinf(av.x) * v0;
                        v1 = sinf(av.y) * v1;
                    }
                    bf h0, l0, h1, l1;
                    bsplit(v0, h0, l0); bsplit(v1, h1, l1);
                    bf* o = Cs + (long)z * csZ + (long)row * 3 * outW + col;
                    __nv_bfloat162 hh; hh.x = h0; hh.y = h1;
                    __nv_bfloat162 ll; ll.x = l0; ll.y = l1;
                    *(__nv_bfloat162*)(o) = hh;
                    *(__nv_bfloat162*)(o + outW) = hh;
                    *(__nv_bfloat162*)(o + 2 * outW) = ll;
                }
            }
        }
    }
}

// ---------------- prep kernels ----------------
// transpose + split: fp32 [R,C] -> bf16 [C, 3R]. SCHEME 0=A[hi,hi,lo] 1=B[hi,lo,hi]
template<int SCHEME>
__global__ void transS(const float* __restrict__ in, bf* __restrict__ out,
                       int R, int C, long inZ, long outZ)
{
    __shared__ float t[32][33];
    int z = blockIdx.z;
    const float* iz = in + (long)z * inZ;
    bf* oz = out + (long)z * outZ;
    int c0 = blockIdx.x * 32, r0 = blockIdx.y * 32;
    int tx = threadIdx.x & 31, ty = threadIdx.x >> 5;
#pragma unroll
    for (int i = 0; i < 32; i += 8)
        t[ty + i][tx] = iz[(long)(r0 + ty + i) * C + c0 + tx];
    __syncthreads();
#pragma unroll
    for (int i = 0; i < 32; i += 8) {
        float v = t[tx][ty + i];
        bf h, l; bsplit(v, h, l);
        long base = (long)(c0 + ty + i) * 3 * R + r0 + tx;
        if (SCHEME == 0) { oz[base] = h; oz[base + R] = h; oz[base + 2L * R] = l; }
        else             { oz[base] = h; oz[base + R] = l; oz[base + 2L * R] = h; }
    }
}

__global__ void silu_kernel(const float* __restrict__ in, float* __restrict__ o) {
    int i = blockIdx.x * 256 + threadIdx.x;
    if (i < B_ * D_) { float v = in[i]; o[i] = v / (1.f + expf(-v)); }
}

__global__ void __launch_bounds__(128) ada_kernel(const float* __restrict__ sl,
    const float* __restrict__ W, const float* __restrict__ bias, float* __restrict__ ada)
{
    __shared__ float s[B_ * D_];
    int col = blockIdx.x * 128 + threadIdx.x;
    for (int i = threadIdx.x; i < B_ * D_; i += 128) s[i] = sl[i];
    __syncthreads();
    float a0 = 0.f, a1 = 0.f, a2 = 0.f, a3 = 0.f;
    for (int k = 0; k < D_; k++) {
        float w = W[(long)k * ADA6 + col];
        a0 = fmaf(s[k], w, a0); a1 = fmaf(s[D_ + k], w, a1);
        a2 = fmaf(s[2 * D_ + k], w, a2); a3 = fmaf(s[3 * D_ + k], w, a3);
    }
    float bv = bias[col];
    ada[col] = a0 + bv; ada[ADA6 + col] = a1 + bv;
    ada[2L * ADA6 + col] = a2 + bv; ada[3L * ADA6 + col] = a3 + bv;
}

// LN width 1024; optional adaLN modulate; optional fp32 out; optional A-scheme split out
__global__ void __launch_bounds__(256) ln_kernel(const float* __restrict__ in,
    float* __restrict__ outF, bf* __restrict__ outS,
    const float* __restrict__ w, const float* __restrict__ b,
    const float* __restrict__ scale, const float* __restrict__ shift,
    int adaStride, float eps)
{
    long row = blockIdx.x;
    const float* xr = in + row * D_;
    int t = threadIdx.x;
    float4 v = *(const float4*)&xr[t * 4];
    float s1 = v.x + v.y + v.z + v.w;
    float s2 = v.x*v.x + v.y*v.y + v.z*v.z + v.w*v.w;
    __shared__ float sm[16];
#pragma unroll
    for (int o = 16; o; o >>= 1) {
        s1 += __shfl_down_sync(0xffffffffu, s1, o);
        s2 += __shfl_down_sync(0xffffffffu, s2, o);
    }
    if ((t & 31) == 0) { sm[t >> 5] = s1; sm[8 + (t >> 5)] = s2; }
    __syncthreads();
    if (t == 0) {
        float a = 0.f, c = 0.f;
        for (int i = 0; i < 8; i++) { a += sm[i]; c += sm[8 + i]; }
        sm[0] = a; sm[8] = c;
    }
    __syncthreads();
    float mean = sm[0] * (1.f / D_);
    float var = sm[8] * (1.f / D_) - mean * mean;
    float rs = rsqrtf(var + eps);
    int c0 = t * 4;
    float4 wv = *(const float4*)&w[c0];
    float4 bv = *(const float4*)&b[c0];
    float o4[4];
    o4[0] = (v.x - mean) * rs * wv.x + bv.x;
    o4[1] = (v.y - mean) * rs * wv.y + bv.y;
    o4[2] = (v.z - mean) * rs * wv.z + bv.z;
    o4[3] = (v.w - mean) * rs * wv.w + bv.w;
    if (scale) {
        int bb = (int)(row >> 10);
        float4 sv = *(const float4*)&scale[(long)bb * adaStride + c0];
        float4 hv = *(const float4*)&shift[(long)bb * adaStride + c0];
        o4[0] = o4[0] * (1.f + sv.x) + hv.x;
        o4[1] = o4[1] * (1.f + sv.y) + hv.y;
        o4[2] = o4[2] * (1.f + sv.z) + hv.z;
        o4[3] = o4[3] * (1.f + sv.w) + hv.w;
    }
    if (outF)
        *(float4*)&outF[row * D_ + c0] = make_float4(o4[0], o4[1], o4[2], o4[3]);
    if (outS) {
        bf* os = outS + row * (long)K3D;
#pragma unroll
        for (int u = 0; u < 4; u++) {
            bf h, l; bsplit(o4[u], h, l);
            os[c0 + u] = h; os[D_ + c0 + u] = h; os[2 * D_ + c0 + u] = l;
        }
    }
}

// softmax width 1024, output bf16 B-scheme split [hi|lo|hi]
__global__ void __launch_bounds__(256) softmax_kernel(const float* __restrict__ p, bf* __restrict__ outS) {
    long row = blockIdx.x;
    const float* r = p + row * D_;
    int t = threadIdx.x;
    float4 v = *(const float4*)&r[t * 4];
    float m = fmaxf(fmaxf(v.x, v.y), fmaxf(v.z, v.w));
    __shared__ float sm[8];
#pragma unroll
    for (int o = 16; o; o >>= 1) m = fmaxf(m, __shfl_down_sync(0xffffffffu, m, o));
    if ((t & 31) == 0) sm[t >> 5] = m;
    __syncthreads();
    if (t == 0) { float a = sm[0]; for (int i = 1; i < 8; i++) a = fmaxf(a, sm[i]); sm[0] = a; }
    __syncthreads();
    m = sm[0];
    float e0 = expf(v.x - m), e1 = expf(v.y - m), e2 = expf(v.z - m), e3 = expf(v.w - m);
    float s = e0 + e1 + e2 + e3;
    __syncthreads();
#pragma unroll
    for (int o = 16; o; o >>= 1) s += __shfl_down_sync(0xffffffffu, s, o);
    if ((t & 31) == 0) sm[t >> 5] = s;
    __syncthreads();
    if (t == 0) { float a = 0.f; for (int i = 0; i < 8; i++) a += sm[i]; sm[0] = a; }
    __syncthreads();
    float inv = 1.f / sm[0];
    float o4[4] = { e0 * inv, e1 * inv, e2 * inv, e3 * inv };
    bf* os = outS + row * (long)K3D;
    int c0 = t * 4;
#pragma unroll
    for (int u = 0; u < 4; u++) {
        bf h, l; bsplit(o4[u], h, l);
        os[c0 + u] = h; os[D_ + c0 + u] = l; os[2 * D_ + c0 + u] = h;
    }
}

__global__ void __launch_bounds__(256) router_kernel(const float* __restrict__ h,
    const float* __restrict__ rw, const float* __restrict__ rb, float* __restrict__ lg)
{
    int tok = blockIdx.x;
    const float* hr = h + (long)tok * D_;
    int t = threadIdx.x;
    float4 hv = *(const float4*)&hr[t * 4];
    float hvv[4] = { hv.x, hv.y, hv.z, hv.w };
    float a0 = 0.f, a1 = 0.f, a2 = 0.f, a3 = 0.f;
#pragma unroll
    for (int j = 0; j < 4; j++) {
        int k = t * 4 + j;
        float4 w = *(const float4*)&rw[(long)k * 4];
        float xv = hvv[j];
        a0 = fmaf(xv, w.x, a0); a1 = fmaf(xv, w.y, a1);
        a2 = fmaf(xv, w.z, a2); a3 = fmaf(xv, w.w, a3);
    }
#pragma unroll
    for (int o = 16; o; o >>= 1) {
        a0 += __shfl_down_sync(0xffffffffu, a0, o);
        a1 += __shfl_down_sync(0xffffffffu, a1, o);
        a2 += __shfl_down_sync(0xffffffffu, a2, o);
        a3 += __shfl_down_sync(0xffffffffu, a3, o);
    }
    __shared__ float sm[8][4];
    if ((t & 31) == 0) { int w5 = t >> 5; sm[w5][0]=a0; sm[w5][1]=a1; sm[w5][2]=a2; sm[w5][3]=a3; }
    __syncthreads();
    if (t < 4) {
        float s = 0.f;
        for (int i = 0; i < 8; i++) s += sm[i][t];
        lg[(long)tok * 4 + t] = s + rb[t];
    }
}

__global__ void __launch_bounds__(256) seqnorm_kernel(float* __restrict__ lg) {
    int b = blockIdx.x >> 2, e = blockIdx.x & 3;
    int t = threadIdx.x;
    float s = 0.f;
    for (int i = t; i < S_; i += 256) {
        float v = lg[((long)(b * S_ + i)) * 4 + e];
        s += v * v;
    }
    __shared__ float sm[8];
#pragma unroll
    for (int o = 16; o; o >>= 1) s += __shfl_down_sync(0xffffffffu, s, o);
    if ((t & 31) == 0) sm[t >> 5] = s;
    __syncthreads();
    if (t == 0) {
        float a = 0.f;
        for (int i = 0; i < 8; i++) a += sm[i];
        sm[0] = 1.f / fmaxf(sqrtf(a), 1e-12f);
    }
    __syncthreads();
    float sc = sm[0];
    for (int i = t; i < S_; i += 256) lg[((long)(b * S_ + i)) * 4 + e] *= sc;
}

__global__ void zero_kernel(int* cnt) { if (threadIdx.x < E_) cnt[threadIdx.x] = 0; }

__global__ void topk_kernel(const float* __restrict__ lg, float* __restrict__ pr,
    int* __restrict__ cnt, int* __restrict__ list,
    int* __restrict__ te, int* __restrict__ tp, float* __restrict__ tw)
{
    int tok = blockIdx.x * 256 + threadIdx.x;
    if (tok >= BS_) return;
    float l[4];
#pragma unroll
    for (int e = 0; e < 4; e++) l[e] = lg[(long)tok * 4 + e];
    float m = fmaxf(fmaxf(l[0], l[1]), fmaxf(l[2], l[3]));
    float p[4]; float s = 0.f;
#pragma unroll
    for (int e = 0; e < 4; e++) { p[e] = expf(l[e] - m); s += p[e]; }
    float inv = 1.f / s;
#pragma unroll
    for (int e = 0; e < 4; e++) { p[e] *= inv; pr[(long)tok * 4 + e] = p[e]; }
    int a0 = 0;
#pragma unroll
    for (int e = 1; e < 4; e++) if (p[e] > p[a0]) a0 = e;
    int a1 = -1; float pb = -1.f;
#pragma unroll
    for (int e = 0; e < 4; e++) if (e != a0 && p[e] > pb) { pb = p[e]; a1 = e; }
    int s0 = atomicAdd(&cnt[a0], 1); list[a0 * CAP + s0] = tok;
    int s1 = atomicAdd(&cnt[a1], 1); list[a1 * CAP + s1] = tok;
    te[2 * tok] = a0;     tp[2 * tok] = s0;     tw[2 * tok] = p[a0];
    te[2 * tok + 1] = a1; tp[2 * tok + 1] = s1; tw[2 * tok + 1] = p[a1];
}

__global__ void combine_kernel(const float* __restrict__ ebuf,
    const int* __restrict__ te, const int* __restrict__ tp,
    const float* __restrict__ tw, float* __restrict__ out)
{
    long gid = (long)blockIdx.x * 256 + threadIdx.x;
    int tok = (int)(gid >> 10);
    int d = (int)(gid & 1023);
    int e0 = te[2 * tok], e1 = te[2 * tok + 1];
    long r0 = ((long)e0 * CAP + tp[2 * tok]) * D_ + d;
    long r1 = ((long)e1 * CAP + tp[2 * tok + 1]) * D_ + d;
    out[gid] = tw[2 * tok] * ebuf[r0] + tw[2 * tok + 1] * ebuf[r1];
}

__global__ void __launch_bounds__(256) aux_kernel(const float* __restrict__ pr,
                                                  float* __restrict__ out, long out_size)
{
    int t = threadIdx.x;
    float acc = 0.f;
    for (int i = t; i < S_ * E_; i += 256) {
        int s = i >> 2, e = i & 3;
        float av = 0.f;
#pragma unroll
        for (int b = 0; b < B_; b++) av += pr[((long)(b * S_ + s)) * 4 + e];
        av *= 0.25f;
        float d = 0.25f - av;
        acc += d * d;
    }
    __shared__ float sm[8];
#pragma unroll
    for (int o = 16; o; o >>= 1) acc += __shfl_down_sync(0xffffffffu, acc, o);
    if ((t & 31) == 0) sm[t >> 5] = acc;
    __syncthreads();
    if (t == 0) {
        float a = 0.f;
        for (int i = 0; i < 8; i++) a += sm[i];
        for (long i = BSD; i < out_size; i++) out[i] = a;
    }
}

// ---------------- host launcher ----------------
extern "C" void kernel_launch(void* const* d_in, const int* in_sizes, int n_in,
                              void* d_out, int out_size)
{
    (void)in_sizes; (void)n_in;
    const float* x     = (const float*)d_in[0];
    const float* adaln = (const float*)d_in[2];
    const float* wq    = (const float*)d_in[3];
    const float* wk    = (const float*)d_in[4];
    const float* wv    = (const float*)d_in[5];
    const float* wo    = (const float*)d_in[6];
    const float* qnw   = (const float*)d_in[7];
    const float* qnb   = (const float*)d_in[8];
    const float* knw   = (const float*)d_in[9];
    const float* knb   = (const float*)d_in[10];
    const float* anw   = (const float*)d_in[11];
    const float* anb   = (const float*)d_in[12];
    const float* fnw   = (const float*)d_in[13];
    const float* fnb   = (const float*)d_in[14];
    const float* w1    = (const float*)d_in[15];
    const float* w2    = (const float*)d_in[16];
    const float* w3    = (const float*)d_in[17];
    const float* rw    = (const float*)d_in[18];
    const float* rb    = (const float*)d_in[19];
    const float* adaw  = (const float*)d_in[20];
    const float* adab  = (const float*)d_in[21];
    float* out = (float*)d_out;

    float *silu_, *ada_, *q_, *k_, *sc_, *x1_, *h2_, *lg_, *pr_, *buf1_, *ebuf_, *tw_;
    bf *hs_, *wqT_, *wkT_, *wvT_, *woT_, *qT_, *kT_, *vs_, *at_, *aos_, *h2s_, *w1T_, *w3T_, *w2T_, *gs_;
    int *cnt_, *list_, *te_, *tp_;
    cudaGetSymbolAddress((void**)&silu_, g_silu);
    cudaGetSymbolAddress((void**)&ada_,  g_ada);
    cudaGetSymbolAddress((void**)&hs_,   g_hs);
    cudaGetSymbolAddress((void**)&wqT_,  g_wqT);
    cudaGetSymbolAddress((void**)&wkT_,  g_wkT);
    cudaGetSymbolAddress((void**)&wvT_,  g_wvT);
    cudaGetSymbolAddress((void**)&woT_,  g_woT);
    cudaGetSymbolAddress((void**)&q_,    g_q);
    cudaGetSymbolAddress((void**)&k_,    g_k);
    cudaGetSymbolAddress((void**)&qT_,   g_qT);
    cudaGetSymbolAddress((void**)&kT_,   g_kT);
    cudaGetSymbolAddress((void**)&vs_,   g_vs);
    cudaGetSymbolAddress((void**)&sc_,   g_sc);
    cudaGetSymbolAddress((void**)&at_,   g_at);
    cudaGetSymbolAddress((void**)&aos_,  g_aos);
    cudaGetSymbolAddress((void**)&x1_,   g_x1);
    cudaGetSymbolAddress((void**)&h2_,   g_h2);
    cudaGetSymbolAddress((void**)&h2s_,  g_h2s);
    cudaGetSymbolAddress((void**)&w1T_,  g_w1T);
    cudaGetSymbolAddress((void**)&w3T_,  g_w3T);
    cudaGetSymbolAddress((void**)&w2T_,  g_w2T);
    cudaGetSymbolAddress((void**)&buf1_, g_buf1);
    cudaGetSymbolAddress((void**)&gs_,   g_gs);
    cudaGetSymbolAddress((void**)&ebuf_, g_ebuf);
    cudaGetSymbolAddress((void**)&lg_,   g_lg);
    cudaGetSymbolAddress((void**)&pr_,   g_pr);
    cudaGetSymbolAddress((void**)&tw_,   g_tw);
    cudaGetSymbolAddress((void**)&cnt_,  g_cnt);
    cudaGetSymbolAddress((void**)&list_, g_list);
    cudaGetSymbolAddress((void**)&te_,   g_te);
    cudaGetSymbolAddress((void**)&tp_,   g_tp);

    cudaFuncSetAttribute(tcgemm<0,false>, cudaFuncAttributeMaxDynamicSharedMemorySize, SMEMSZ);
    cudaFuncSetAttribute(tcgemm<1,false>, cudaFuncAttributeMaxDynamicSharedMemorySize, SMEMSZ);
    cudaFuncSetAttribute(tcgemm<2,false>, cudaFuncAttributeMaxDynamicSharedMemorySize, SMEMSZ);
    cudaFuncSetAttribute(tcgemm<0,true>,  cudaFuncAttributeMaxDynamicSharedMemorySize, SMEMSZ);
    cudaFuncSetAttribute(tcgemm<3,true>,  cudaFuncAttributeMaxDynamicSharedMemorySize, SMEMSZ);

    const float eps = 1e-5f;

    // adaLN vectors
    silu_kernel<<<(B_*D_ + 255)/256, 256>>>(adaln, silu_);
    ada_kernel<<<ADA6/128, 128>>>(silu_, adaw, adab, ada_);

    // weight prep (transpose + B-scheme split)
    transS<1><<<dim3(D_/32, D_/32, 1), 256>>>(wq, wqT_, D_, D_, 0, 0);
    transS<1><<<dim3(D_/32, D_/32, 1), 256>>>(wk, wkT_, D_, D_, 0, 0);
    transS<1><<<dim3(D_/32, D_/32, 1), 256>>>(wv, wvT_, D_, D_, 0, 0);
    transS<1><<<dim3(D_/32, D_/32, 1), 256>>>(wo, woT_, D_, D_, 0, 0);
    transS<1><<<dim3(H_/32, D_/32, E_), 256>>>(w1, w1T_, D_, H_, (long)D_*H_, (long)H_*K3D);
    transS<1><<<dim3(H_/32, D_/32, E_), 256>>>(w3, w3T_, D_, H_, (long)D_*H_, (long)H_*K3D);
    transS<1><<<dim3(D_/32, H_/32, E_), 256>>>(w2, w2T_, H_, D_, (long)H_*D_, (long)D_*K3H);

    // h = modulate(LN(x), msa) -> A-scheme split
    ln_kernel<<<BS_, 256>>>(x, nullptr, hs_, anw, anb, ada_ + D_, ada_, ADA6, eps);

    // q,k (fp32), v (A-scheme split)
    tcgemm<0,false><<<dim3(32,8,1), 256, SMEMSZ>>>(hs_, 0, wqT_, 0, K3D, D_, BS_,
        nullptr, nullptr, q_, 0, nullptr, 0, 0, nullptr, 0, nullptr, 0);
    tcgemm<0,false><<<dim3(32,8,1), 256, SMEMSZ>>>(hs_, 0, wkT_, 0, K3D, D_, BS_,
        nullptr, nullptr, k_, 0, nullptr, 0, 0, nullptr, 0, nullptr, 0);
    tcgemm<2,false><<<dim3(32,8,1), 256, SMEMSZ>>>(hs_, 0, wvT_, 0, K3D, D_, BS_,
        nullptr, nullptr, nullptr, 0, vs_, D_, 0, nullptr, 0, nullptr, 0);

    // q_norm / k_norm then transpose-split per batch
    ln_kernel<<<BS_, 256>>>(q_, q_, nullptr, qnw, qnb, nullptr, nullptr, 0, eps);
    ln_kernel<<<BS_, 256>>>(k_, k_, nullptr, knw, knb, nullptr, nullptr, 0, eps);
    transS<0><<<dim3(D_/32, S_/32, B_), 256>>>(q_, qT_, S_, D_, (long)S_*D_, (long)D_*K3S);
    transS<1><<<dim3(D_/32, S_/32, B_), 256>>>(k_, kT_, S_, D_, (long)S_*D_, (long)D_*K3S);

    // scores[b] = q^T k
    tcgemm<0,false><<<dim3(8,8,B_), 256, SMEMSZ>>>(qT_, (long)D_*K3S, kT_, (long)D_*K3S,
        K3S, D_, D_, nullptr, nullptr, sc_, (long)D_*D_, nullptr, 0, 0, nullptr, 0, nullptr, 0);

    // softmax -> B-scheme split
    softmax_kernel<<<B_*D_, 256>>>(sc_, at_);

    // ao[b] = v @ attn^T -> A-scheme split
    tcgemm<2,false><<<dim3(8,8,B_), 256, SMEMSZ>>>(vs_, (long)S_*K3D, at_, (long)D_*K3D,
        K3D, D_, S_, nullptr, nullptr, nullptr, 0, aos_, D_, (long)S_*K3D, nullptr, 0, nullptr, 0);

    // x1 = x + gate_msa * (ao @ wo)
    tcgemm<1,false><<<dim3(32,8,1), 256, SMEMSZ>>>(aos_, 0, woT_, 0, K3D, D_, BS_,
        nullptr, nullptr, x1_, 0, nullptr, 0, 0, x, 0, ada_ + 2L*D_, ADA6);

    // h2 = modulate(LN(x1), mlp): fp32 + split
    ln_kernel<<<BS_, 256>>>(x1_, h2_, h2s_, fnw, fnb, ada_ + 4L*D_, ada_ + 3L*D_, ADA6, eps);

    // router + dispatch (exact fp32)
    router_kernel<<<BS_, 256>>>(h2_, rw, rb, lg_);
    seqnorm_kernel<<<B_*E_, 256>>>(lg_);
    zero_kernel<<<1, 32>>>(cnt_);
    topk_kernel<<<BS_/256, 256>>>(lg_, pr_, cnt_, list_, te_, tp_, tw_);

    // expert up: h1 fp32; gated = sin(h1)*h3 -> A-scheme split
    tcgemm<0,true><<<dim3(CAP/128, H_/128, E_), 256, SMEMSZ>>>(h2s_, 0, w1T_, (long)H_*K3D,
        K3D, H_, CAP, cnt_, list_, buf1_, (long)CAP*H_, nullptr, 0, 0, nullptr, 0, nullptr, 0);
    tcgemm<3,true><<<dim3(CAP/128, H_/128, E_), 256, SMEMSZ>>>(h2s_, 0, w3T_, (long)H_*K3D,
        K3D, H_, CAP, cnt_, list_, nullptr, 0, gs_, H_, (long)CAP*K3H, buf1_, (long)CAP*H_, nullptr, 0);

    // expert down
    tcgemm<0,false><<<dim3(CAP/128, D_/128, E_), 256, SMEMSZ>>>(gs_, (long)CAP*K3H, w2T_, (long)D_*K3H,
        K3H, D_, CAP, cnt_, nullptr, ebuf_, (long)CAP*D_, nullptr, 0, 0, nullptr, 0, nullptr, 0);

    // combine + aux
    combine_kernel<<<(int)(BSD/256), 256>>>(ebuf_, te_, tp_, tw_, out);
    aux_kernel<<<1, 256>>>(pr_, out, (long)out_size);
}

// round 5
// speedup vs baseline: 2.7698x; 1.0746x over previous
#include <cuda_runtime.h>
#include <cuda_bf16.h>
#include <math.h>

typedef unsigned int u32;
typedef __nv_bfloat16 bf;

#define B_  4
#define S_  1024
#define D_  1024
#define E_  4
#define H_  2816
#define BS_ (B_*S_)
#define CAP BS_
#define ADA6 (6*D_)
#define BSD ((long)BS_*D_)
#define K2D 2048
#define K2H (2*H_)
#define STG1 49152
#define SMEM1 (4*STG1)   // hgemm: 4 stages x (A 32KB + B 16KB)
#define SMEM2 (4*STG1)   // hgemm2: 4 stages x (A 16KB + B1 16KB + B2 16KB)

// ---------------- device scratch ----------------
__device__ __align__(16) float g_silu[B_*D_];
__device__ __align__(16) float g_ada [B_*ADA6];
__device__ __align__(16) bf    g_hs  [(long)BS_*K2D];
__device__ __align__(16) bf    g_wqT [(long)D_*K2D];
__device__ __align__(16) bf    g_wkT [(long)D_*K2D];
__device__ __align__(16) bf    g_wvT [(long)D_*K2D];
__device__ __align__(16) bf    g_woT [(long)D_*K2D];
__device__ __align__(16) float g_q   [BS_*D_];
__device__ __align__(16) float g_k   [BS_*D_];
__device__ __align__(16) bf    g_qT  [(long)B_*D_*K2D];
__device__ __align__(16) bf    g_kT  [(long)B_*D_*K2D];
__device__ __align__(16) bf    g_vs  [(long)BS_*K2D];
__device__ __align__(16) float g_sc  [(long)B_*D_*D_];
__device__ __align__(16) bf    g_at  [(long)B_*D_*K2D];
__device__ __align__(16) bf    g_aos [(long)BS_*K2D];
__device__ __align__(16) float g_x1  [BS_*D_];
__device__ __align__(16) float g_h2  [BS_*D_];
__device__ __align__(16) bf    g_h2s [(long)BS_*K2D];
__device__ __align__(16) bf    g_w1T [(long)E_*H_*K2D];
__device__ __align__(16) bf    g_w3T [(long)E_*H_*K2D];
__device__ __align__(16) bf    g_w2T [(long)E_*D_*K2H];
__device__ __align__(16) bf    g_gs  [(long)E_*CAP*K2H];
__device__ __align__(16) float g_ebuf[(long)E_*CAP*D_];
__device__ __align__(16) float g_lg  [BS_*E_];
__device__ __align__(16) float g_pr  [BS_*E_];
__device__ int   g_cnt [E_];
__device__ int   g_list[E_*CAP];
__device__ int   g_te  [BS_*2];
__device__ int   g_tp  [BS_*2];
__device__ __align__(16) float g_tw  [BS_*2];

// ---------------- helpers ----------------
__device__ __forceinline__ u32 smem_u32(const void* p) {
    u32 a;
    asm("{ .reg .u64 t; cvta.to.shared.u64 t, %1; cvt.u32.u64 %0, t; }" : "=r"(a) : "l"(p));
    return a;
}
__device__ __forceinline__ u32 swz(u32 o) { return o ^ ((o >> 3) & 0x70); }
__device__ __forceinline__ void bsplit(float v, bf& h, bf& l) {
    h = __float2bfloat16(v);
    l = __float2bfloat16(v - __bfloat162float(h));
}
#define CP16(dst, src) asm volatile("cp.async.cg.shared.global [%0], [%1], 16;" :: "r"(dst), "l"(src))
#define CP_COMMIT()    asm volatile("cp.async.commit_group;")
#define CP_WAIT2()     asm volatile("cp.async.wait_group 2;")
#define LDM4(r, ad) asm volatile("ldmatrix.sync.aligned.m8n8.x4.shared.b16 {%0,%1,%2,%3}, [%4];" \
    : "=r"((r)[0]), "=r"((r)[1]), "=r"((r)[2]), "=r"((r)[3]) : "r"(ad))
#define MMA(c, a, b0, b1) asm volatile( \
    "mma.sync.aligned.m16n8k16.row.col.f32.bf16.bf16.f32 " \
    "{%0,%1,%2,%3}, {%4,%5,%6,%7}, {%8,%9}, {%0,%1,%2,%3};" \
    : "+f"((c)[0]), "+f"((c)[1]), "+f"((c)[2]), "+f"((c)[3]) \
    : "r"((a)[0]), "r"((a)[1]), "r"((a)[2]), "r"((a)[3]), "r"(b0), "r"(b1))

// ============ single-B GEMM: C[M,N] = A[M,2K](3seg) * B[N,2K](3seg)^T ============
// 256x128 CTA tile, 8 warps of 64x64, 4-stage cp.async.
// seg map: A planes hi,hi,lo  B planes hi,lo,hi
// EPI 0: fp32 store   1: resid + gate*acc (fp32)   2: split [hi|lo] bf16 store
template<int EPI, bool GATHER>
__global__ void __launch_bounds__(256, 1) hgemm(
    const bf* __restrict__ A, long aZ,
    const bf* __restrict__ Bm, long bZ,
    int Kr, int N, int Mcap,
    const int* __restrict__ counts, const int* __restrict__ list,
    float* __restrict__ Cf, long cZ,
    bf* __restrict__ Cs, int outW, long csZ,
    const float* __restrict__ aux,
    const float* __restrict__ gate, int gateStride)
{
    extern __shared__ __align__(16) char smem[];
    const int z = blockIdx.z;
    const int Meff = counts ? counts[z] : Mcap;
    const int m0 = blockIdx.x * 256;
    if (m0 >= Meff) return;
    const int n0 = blockIdx.y * 128;
    const int tid = threadIdx.x, wid = tid >> 5, lane = tid & 31;
    const int wm = wid >> 1, wn = wid & 1;
    const u32 sb = smem_u32(smem);
    const long K2 = 2L * Kr;

    const bf* Az = A + (long)z * aZ;
    const bf* Bz = Bm + (long)z * bZ;

    // per-thread load rows
    long aRow[8];
    int  jA = tid & 7;
#pragma unroll
    for (int i = 0; i < 8; i++) {
        int r = (i * 256 + tid) >> 3;
        int gm = m0 + r; if (gm > Meff - 1) gm = Meff - 1;
        aRow[i] = GATHER ? (long)list[(long)z * CAP + gm] : (long)gm;
    }
    u32 dA[8], dB[4];
#pragma unroll
    for (int i = 0; i < 8; i++) { int r = (i * 256 + tid) >> 3; dA[i] = swz((u32)(r * 128 + jA * 16)); }
#pragma unroll
    for (int i = 0; i < 4; i++) { int r = (i * 256 + tid) >> 3; dB[i] = swz((u32)(r * 128 + jA * 16)); }

    float acc[4][8][4];
#pragma unroll
    for (int a = 0; a < 4; a++)
#pragma unroll
        for (int b = 0; b < 8; b++)
#pragma unroll
            for (int c = 0; c < 4; c++) acc[a][b][c] = 0.f;

    const int seglen = Kr >> 6;
    const int NC = 3 * seglen;

    auto issue = [&](int c) {
        int seg = c / seglen;
        int kin = (c - seg * seglen) << 6;
        int aOff = (seg == 2 ? Kr : 0) + kin + jA * 8;
        int bOff = (seg == 1 ? Kr : 0) + kin + jA * 8;
        u32 base = sb + (u32)(c & 3) * STG1;
#pragma unroll
        for (int i = 0; i < 8; i++)
            CP16(base + dA[i], Az + aRow[i] * K2 + aOff);
#pragma unroll
        for (int i = 0; i < 4; i++) {
            int r = (i * 256 + tid) >> 3;
            CP16(base + 32768 + dB[i], Bz + (long)(n0 + r) * K2 + bOff);
        }
    };

    issue(0); CP_COMMIT();
    issue(1); CP_COMMIT();
    issue(2); CP_COMMIT();

    for (int c = 0; c < NC; c++) {
        CP_WAIT2();
        __syncthreads();
        if (c + 3 < NC) issue(c + 3);
        CP_COMMIT();
        u32 aB = sb + (u32)(c & 3) * STG1, bB = aB + 32768;
#pragma unroll
        for (int s = 0; s < 4; s++) {
            u32 afr[4][4], bfr[4][4];
#pragma unroll
            for (int mi = 0; mi < 4; mi++) {
                int row = wm * 64 + mi * 16 + (lane & 7) + ((lane >> 3) & 1) * 8;
                int kb = s * 32 + (lane >> 4) * 16;
                LDM4(afr[mi], aB + swz((u32)(row * 128 + kb)));
            }
#pragma unroll
            for (int ni = 0; ni < 4; ni++) {
                int nrow = wn * 64 + ni * 16 + (lane & 7) + (lane >> 4) * 8;
                int kb = s * 32 + ((lane >> 3) & 1) * 16;
                LDM4(bfr[ni], bB + swz((u32)(nrow * 128 + kb)));
            }
#pragma unroll
            for (int mi = 0; mi < 4; mi++)
#pragma unroll
                for (int nj = 0; nj < 8; nj++)
                    MMA(acc[mi][nj], afr[mi], bfr[nj >> 1][(nj & 1) * 2], bfr[nj >> 1][(nj & 1) * 2 + 1]);
        }
    }

    // epilogue
#pragma unroll
    for (int mi = 0; mi < 4; mi++) {
#pragma unroll
        for (int half = 0; half < 2; half++) {
            int row = m0 + wm * 64 + mi * 16 + (lane >> 2) + half * 8;
            if (row >= Meff) continue;
#pragma unroll
            for (int nj = 0; nj < 8; nj++) {
                int col = n0 + wn * 64 + nj * 8 + (lane & 3) * 2;
                float v0 = acc[mi][nj][half * 2], v1 = acc[mi][nj][half * 2 + 1];
                if (EPI == 0) {
                    *(float2*)(Cf + (long)z * cZ + (long)row * N + col) = make_float2(v0, v1);
                } else if (EPI == 1) {
                    int bb = row >> 10;
                    const float2 rs = *(const float2*)(aux + (long)row * N + col);
                    const float* gv = gate + (long)bb * gateStride + col;
                    *(float2*)(Cf + (long)row * N + col) = make_float2(rs.x + gv[0] * v0, rs.y + gv[1] * v1);
                } else {
                    bf h0, l0, h1, l1;
                    bsplit(v0, h0, l0); bsplit(v1, h1, l1);
                    bf* o = Cs + (long)z * csZ + (long)row * 2 * outW + col;
                    __nv_bfloat162 hh; hh.x = h0; hh.y = h1;
                    __nv_bfloat162 ll; ll.x = l0; ll.y = l1;
                    *(__nv_bfloat162*)(o) = hh;
                    *(__nv_bfloat162*)(o + outW) = ll;
                }
            }
        }
    }
}

// ============ dual-B GEMM (MoE up, fused): gs = split(sin(A*B1^T) * (A*B2^T)) ============
// 128x128 CTA tile, 8 warps of 64x32 (x2 accumulators), 4-stage.
__global__ void __launch_bounds__(256, 1) hgemm2(
    const bf* __restrict__ A,
    const bf* __restrict__ B1m, const bf* __restrict__ B2m, long bZ,
    int Kr, int N, int Mcap,
    const int* __restrict__ counts, const int* __restrict__ list,
    bf* __restrict__ Cs, long csZ)
{
    extern __shared__ __align__(16) char smem[];
    const int z = blockIdx.z;
    const int Meff = counts[z];
    const int m0 = blockIdx.x * 128;
    if (m0 >= Meff) return;
    const int n0 = blockIdx.y * 128;
    const int tid = threadIdx.x, wid = tid >> 5, lane = tid & 31;
    const int wm = wid >> 2, wn = wid & 3;
    const u32 sb = smem_u32(smem);
    const long K2 = 2L * Kr;

    const bf* B1z = B1m + (long)z * bZ;
    const bf* B2z = B2m + (long)z * bZ;

    long aRow[4];
    int jA = tid & 7;
#pragma unroll
    for (int i = 0; i < 4; i++) {
        int r = (i * 256 + tid) >> 3;
        int gm = m0 + r; if (gm > Meff - 1) gm = Meff - 1;
        aRow[i] = (long)list[(long)z * CAP + gm];
    }
    u32 dT[4];
#pragma unroll
    for (int i = 0; i < 4; i++) { int r = (i * 256 + tid) >> 3; dT[i] = swz((u32)(r * 128 + jA * 16)); }

    float acc1[4][4][4], acc2[4][4][4];
#pragma unroll
    for (int a = 0; a < 4; a++)
#pragma unroll
        for (int b = 0; b < 4; b++)
#pragma unroll
            for (int c = 0; c < 4; c++) { acc1[a][b][c] = 0.f; acc2[a][b][c] = 0.f; }

    const int seglen = Kr >> 6;
    const int NC = 3 * seglen;

    auto issue = [&](int c) {
        int seg = c / seglen;
        int kin = (c - seg * seglen) << 6;
        int aOff = (seg == 2 ? Kr : 0) + kin + jA * 8;
        int bOff = (seg == 1 ? Kr : 0) + kin + jA * 8;
        u32 base = sb + (u32)(c & 3) * STG1;
#pragma unroll
        for (int i = 0; i < 4; i++) {
            int r = (i * 256 + tid) >> 3;
            CP16(base + dT[i], A + aRow[i] * K2 + aOff);
            CP16(base + 16384 + dT[i], B1z + (long)(n0 + r) * K2 + bOff);
            CP16(base + 32768 + dT[i], B2z + (long)(n0 + r) * K2 + bOff);
        }
    };

    issue(0); CP_COMMIT();
    issue(1); CP_COMMIT();
    issue(2); CP_COMMIT();

    for (int c = 0; c < NC; c++) {
        CP_WAIT2();
        __syncthreads();
        if (c + 3 < NC) issue(c + 3);
        CP_COMMIT();
        u32 aB = sb + (u32)(c & 3) * STG1, b1B = aB + 16384, b2B = aB + 32768;
#pragma unroll
        for (int s = 0; s < 4; s++) {
            u32 afr[4][4], bfr1[2][4], bfr2[2][4];
#pragma unroll
            for (int mi = 0; mi < 4; mi++) {
                int row = wm * 64 + mi * 16 + (lane & 7) + ((lane >> 3) & 1) * 8;
                int kb = s * 32 + (lane >> 4) * 16;
                LDM4(afr[mi], aB + swz((u32)(row * 128 + kb)));
            }
#pragma unroll
            for (int bi = 0; bi < 2; bi++) {
                int nrow = wn * 32 + bi * 16 + (lane & 7) + (lane >> 4) * 8;
                int kb = s * 32 + ((lane >> 3) & 1) * 16;
                LDM4(bfr1[bi], b1B + swz((u32)(nrow * 128 + kb)));
                LDM4(bfr2[bi], b2B + swz((u32)(nrow * 128 + kb)));
            }
#pragma unroll
            for (int mi = 0; mi < 4; mi++)
#pragma unroll
                for (int nj = 0; nj < 4; nj++) {
                    MMA(acc1[mi][nj], afr[mi], bfr1[nj >> 1][(nj & 1) * 2], bfr1[nj >> 1][(nj & 1) * 2 + 1]);
                    MMA(acc2[mi][nj], afr[mi], bfr2[nj >> 1][(nj & 1) * 2], bfr2[nj >> 1][(nj & 1) * 2 + 1]);
                }
        }
    }

#pragma unroll
    for (int mi = 0; mi < 4; mi++) {
#pragma unroll
        for (int half = 0; half < 2; half++) {
            int row = m0 + wm * 64 + mi * 16 + (lane >> 2) + half * 8;
            if (row >= Meff) continue;
#pragma unroll
            for (int nj = 0; nj < 4; nj++) {
                int col = n0 + wn * 32 + nj * 8 + (lane & 3) * 2;
                float v0 = sinf(acc1[mi][nj][half * 2]) * acc2[mi][nj][half * 2];
                float v1 = sinf(acc1[mi][nj][half * 2 + 1]) * acc2[mi][nj][half * 2 + 1];
                bf h0, l0, h1, l1;
                bsplit(v0, h0, l0); bsplit(v1, h1, l1);
                bf* o = Cs + (long)z * csZ + (long)row * (long)(2 * N) + col;
                __nv_bfloat162 hh; hh.x = h0; hh.y = h1;
                __nv_bfloat162 ll; ll.x = l0; ll.y = l1;
                *(__nv_bfloat162*)(o) = hh;
                *(__nv_bfloat162*)(o + N) = ll;
            }
        }
    }
}

// ---------------- prep kernels ----------------
// transpose + split: fp32 [R,C] -> bf16 [C, 2R] planes [hi|lo]
__global__ void transS(const float* __restrict__ in, bf* __restrict__ out,
                       int R, int C, long inZ, long outZ)
{
    __shared__ float t[32][33];
    int z = blockIdx.z;
    const float* iz = in + (long)z * inZ;
    bf* oz = out + (long)z * outZ;
    int c0 = blockIdx.x * 32, r0 = blockIdx.y * 32;
    int tx = threadIdx.x & 31, ty = threadIdx.x >> 5;
#pragma unroll
    for (int i = 0; i < 32; i += 8)
        t[ty + i][tx] = iz[(long)(r0 + ty + i) * C + c0 + tx];
    __syncthreads();
#pragma unroll
    for (int i = 0; i < 32; i += 8) {
        float v = t[tx][ty + i];
        bf h, l; bsplit(v, h, l);
        long base = (long)(c0 + ty + i) * 2 * R + r0 + tx;
        oz[base] = h; oz[base + R] = l;
    }
}

__global__ void silu_kernel(const float* __restrict__ in, float* __restrict__ o) {
    int i = blockIdx.x * 256 + threadIdx.x;
    if (i < B_ * D_) { float v = in[i]; o[i] = v / (1.f + expf(-v)); }
}

__global__ void __launch_bounds__(128) ada_kernel(const float* __restrict__ sl,
    const float* __restrict__ W, const float* __restrict__ bias, float* __restrict__ ada)
{
    __shared__ float s[B_ * D_];
    int col = blockIdx.x * 128 + threadIdx.x;
    for (int i = threadIdx.x; i < B_ * D_; i += 128) s[i] = sl[i];
    __syncthreads();
    float a0 = 0.f, a1 = 0.f, a2 = 0.f, a3 = 0.f;
    for (int k = 0; k < D_; k++) {
        float w = W[(long)k * ADA6 + col];
        a0 = fmaf(s[k], w, a0); a1 = fmaf(s[D_ + k], w, a1);
        a2 = fmaf(s[2 * D_ + k], w, a2); a3 = fmaf(s[3 * D_ + k], w, a3);
    }
    float bv = bias[col];
    ada[col] = a0 + bv; ada[ADA6 + col] = a1 + bv;
    ada[2L * ADA6 + col] = a2 + bv; ada[3L * ADA6 + col] = a3 + bv;
}

__global__ void __launch_bounds__(256) ln_kernel(const float* __restrict__ in,
    float* __restrict__ outF, bf* __restrict__ outS,
    const float* __restrict__ w, const float* __restrict__ b,
    const float* __restrict__ scale, const float* __restrict__ shift,
    int adaStride, float eps)
{
    long row = blockIdx.x;
    const float* xr = in + row * D_;
    int t = threadIdx.x;
    float4 v = *(const float4*)&xr[t * 4];
    float s1 = v.x + v.y + v.z + v.w;
    float s2 = v.x*v.x + v.y*v.y + v.z*v.z + v.w*v.w;
    __shared__ float sm[16];
#pragma unroll
    for (int o = 16; o; o >>= 1) {
        s1 += __shfl_down_sync(0xffffffffu, s1, o);
        s2 += __shfl_down_sync(0xffffffffu, s2, o);
    }
    if ((t & 31) == 0) { sm[t >> 5] = s1; sm[8 + (t >> 5)] = s2; }
    __syncthreads();
    if (t == 0) {
        float a = 0.f, c = 0.f;
        for (int i = 0; i < 8; i++) { a += sm[i]; c += sm[8 + i]; }
        sm[0] = a; sm[8] = c;
    }
    __syncthreads();
    float mean = sm[0] * (1.f / D_);
    float var = sm[8] * (1.f / D_) - mean * mean;
    float rs = rsqrtf(var + eps);
    int c0 = t * 4;
    float4 wv = *(const float4*)&w[c0];
    float4 bv = *(const float4*)&b[c0];
    float o4[4];
    o4[0] = (v.x - mean) * rs * wv.x + bv.x;
    o4[1] = (v.y - mean) * rs * wv.y + bv.y;
    o4[2] = (v.z - mean) * rs * wv.z + bv.z;
    o4[3] = (v.w - mean) * rs * wv.w + bv.w;
    if (scale) {
        int bb = (int)(row >> 10);
        float4 sv = *(const float4*)&scale[(long)bb * adaStride + c0];
        float4 hv = *(const float4*)&shift[(long)bb * adaStride + c0];
        o4[0] = o4[0] * (1.f + sv.x) + hv.x;
        o4[1] = o4[1] * (1.f + sv.y) + hv.y;
        o4[2] = o4[2] * (1.f + sv.z) + hv.z;
        o4[3] = o4[3] * (1.f + sv.w) + hv.w;
    }
    if (outF)
        *(float4*)&outF[row * D_ + c0] = make_float4(o4[0], o4[1], o4[2], o4[3]);
    if (outS) {
        bf* os = outS + row * (long)K2D;
#pragma unroll
        for (int u = 0; u < 4; u++) {
            bf h, l; bsplit(o4[u], h, l);
            os[c0 + u] = h; os[D_ + c0 + u] = l;
        }
    }
}

__global__ void __launch_bounds__(256) softmax_kernel(const float* __restrict__ p, bf* __restrict__ outS) {
    long row = blockIdx.x;
    const float* r = p + row * D_;
    int t = threadIdx.x;
    float4 v = *(const float4*)&r[t * 4];
    float m = fmaxf(fmaxf(v.x, v.y), fmaxf(v.z, v.w));
    __shared__ float sm[8];
#pragma unroll
    for (int o = 16; o; o >>= 1) m = fmaxf(m, __shfl_down_sync(0xffffffffu, m, o));
    if ((t & 31) == 0) sm[t >> 5] = m;
    __syncthreads();
    if (t == 0) { float a = sm[0]; for (int i = 1; i < 8; i++) a = fmaxf(a, sm[i]); sm[0] = a; }
    __syncthreads();
    m = sm[0];
    float e0 = expf(v.x - m), e1 = expf(v.y - m), e2 = expf(v.z - m), e3 = expf(v.w - m);
    float s = e0 + e1 + e2 + e3;
    __syncthreads();
#pragma unroll
    for (int o = 16; o; o >>= 1) s += __shfl_down_sync(0xffffffffu, s, o);
    if ((t & 31) == 0) sm[t >> 5] = s;
    __syncthreads();
    if (t == 0) { float a = 0.f; for (int i = 0; i < 8; i++) a += sm[i]; sm[0] = a; }
    __syncthreads();
    float inv = 1.f / sm[0];
    float o4[4] = { e0 * inv, e1 * inv, e2 * inv, e3 * inv };
    bf* os = outS + row * (long)K2D;
    int c0 = t * 4;
#pragma unroll
    for (int u = 0; u < 4; u++) {
        bf h, l; bsplit(o4[u], h, l);
        os[c0 + u] = h; os[D_ + c0 + u] = l;
    }
}

__global__ void __launch_bounds__(256) router_kernel(const float* __restrict__ h,
    const float* __restrict__ rw, const float* __restrict__ rb, float* __restrict__ lg)
{
    int tok = blockIdx.x;
    const float* hr = h + (long)tok * D_;
    int t = threadIdx.x;
    float4 hv = *(const float4*)&hr[t * 4];
    float hvv[4] = { hv.x, hv.y, hv.z, hv.w };
    float a0 = 0.f, a1 = 0.f, a2 = 0.f, a3 = 0.f;
#pragma unroll
    for (int j = 0; j < 4; j++) {
        int k = t * 4 + j;
        float4 w = *(const float4*)&rw[(long)k * 4];
        float xv = hvv[j];
        a0 = fmaf(xv, w.x, a0); a1 = fmaf(xv, w.y, a1);
        a2 = fmaf(xv, w.z, a2); a3 = fmaf(xv, w.w, a3);
    }
#pragma unroll
    for (int o = 16; o; o >>= 1) {
        a0 += __shfl_down_sync(0xffffffffu, a0, o);
        a1 += __shfl_down_sync(0xffffffffu, a1, o);
        a2 += __shfl_down_sync(0xffffffffu, a2, o);
        a3 += __shfl_down_sync(0xffffffffu, a3, o);
    }
    __shared__ float sm[8][4];
    if ((t & 31) == 0) { int w5 = t >> 5; sm[w5][0]=a0; sm[w5][1]=a1; sm[w5][2]=a2; sm[w5][3]=a3; }
    __syncthreads();
    if (t < 4) {
        float s = 0.f;
        for (int i = 0; i < 8; i++) s += sm[i][t];
        lg[(long)tok * 4 + t] = s + rb[t];
    }
}

__global__ void __launch_bounds__(256) seqnorm_kernel(float* __restrict__ lg) {
    int b = blockIdx.x >> 2, e = blockIdx.x & 3;
    int t = threadIdx.x;
    float s = 0.f;
    for (int i = t; i < S_; i += 256) {
        float v = lg[((long)(b * S_ + i)) * 4 + e];
        s += v * v;
    }
    __shared__ float sm[8];
#pragma unroll
    for (int o = 16; o; o >>= 1) s += __shfl_down_sync(0xffffffffu, s, o);
    if ((t & 31) == 0) sm[t >> 5] = s;
    __syncthreads();
    if (t == 0) {
        float a = 0.f;
        for (int i = 0; i < 8; i++) a += sm[i];
        sm[0] = 1.f / fmaxf(sqrtf(a), 1e-12f);
    }
    __syncthreads();
    float sc = sm[0];
    for (int i = t; i < S_; i += 256) lg[((long)(b * S_ + i)) * 4 + e] *= sc;
}

__global__ void zero_kernel(int* cnt) { if (threadIdx.x < E_) cnt[threadIdx.x] = 0; }

__global__ void topk_kernel(const float* __restrict__ lg, float* __restrict__ pr,
    int* __restrict__ cnt, int* __restrict__ list,
    int* __restrict__ te, int* __restrict__ tp, float* __restrict__ tw)
{
    int tok = blockIdx.x * 256 + threadIdx.x;
    if (tok >= BS_) return;
    float l[4];
#pragma unroll
    for (int e = 0; e < 4; e++) l[e] = lg[(long)tok * 4 + e];
    float m = fmaxf(fmaxf(l[0], l[1]), fmaxf(l[2], l[3]));
    float p[4]; float s = 0.f;
#pragma unroll
    for (int e = 0; e < 4; e++) { p[e] = expf(l[e] - m); s += p[e]; }
    float inv = 1.f / s;
#pragma unroll
    for (int e = 0; e < 4; e++) { p[e] *= inv; pr[(long)tok * 4 + e] = p[e]; }
    int a0 = 0;
#pragma unroll
    for (int e = 1; e < 4; e++) if (p[e] > p[a0]) a0 = e;
    int a1 = -1; float pb = -1.f;
#pragma unroll
    for (int e = 0; e < 4; e++) if (e != a0 && p[e] > pb) { pb = p[e]; a1 = e; }
    int s0 = atomicAdd(&cnt[a0], 1); list[a0 * CAP + s0] = tok;
    int s1 = atomicAdd(&cnt[a1], 1); list[a1 * CAP + s1] = tok;
    te[2 * tok] = a0;     tp[2 * tok] = s0;     tw[2 * tok] = p[a0];
    te[2 * tok + 1] = a1; tp[2 * tok + 1] = s1; tw[2 * tok + 1] = p[a1];
}

__global__ void combine_kernel(const float* __restrict__ ebuf,
    const int* __restrict__ te, const int* __restrict__ tp,
    const float* __restrict__ tw, float* __restrict__ out)
{
    long gid = (long)blockIdx.x * 256 + threadIdx.x;
    int tok = (int)(gid >> 10);
    int d = (int)(gid & 1023);
    int e0 = te[2 * tok], e1 = te[2 * tok + 1];
    long r0 = ((long)e0 * CAP + tp[2 * tok]) * D_ + d;
    long r1 = ((long)e1 * CAP + tp[2 * tok + 1]) * D_ + d;
    out[gid] = tw[2 * tok] * ebuf[r0] + tw[2 * tok + 1] * ebuf[r1];
}

__global__ void __launch_bounds__(256) aux_kernel(const float* __restrict__ pr,
                                                  float* __restrict__ out, long out_size)
{
    int t = threadIdx.x;
    float acc = 0.f;
    for (int i = t; i < S_ * E_; i += 256) {
        int s = i >> 2, e = i & 3;
        float av = 0.f;
#pragma unroll
        for (int b = 0; b < B_; b++) av += pr[((long)(b * S_ + s)) * 4 + e];
        av *= 0.25f;
        float d = 0.25f - av;
        acc += d * d;
    }
    __shared__ float sm[8];
#pragma unroll
    for (int o = 16; o; o >>= 1) acc += __shfl_down_sync(0xffffffffu, acc, o);
    if ((t & 31) == 0) sm[t >> 5] = acc;
    __syncthreads();
    if (t == 0) {
        float a = 0.f;
        for (int i = 0; i < 8; i++) a += sm[i];
        for (long i = BSD; i < out_size; i++) out[i] = a;
    }
}

// ---------------- host launcher ----------------
extern "C" void kernel_launch(void* const* d_in, const int* in_sizes, int n_in,
                              void* d_out, int out_size)
{
    (void)in_sizes; (void)n_in;
    const float* x     = (const float*)d_in[0];
    const float* adaln = (const float*)d_in[2];
    const float* wq    = (const float*)d_in[3];
    const float* wk    = (const float*)d_in[4];
    const float* wv    = (const float*)d_in[5];
    const float* wo    = (const float*)d_in[6];
    const float* qnw   = (const float*)d_in[7];
    const float* qnb   = (const float*)d_in[8];
    const float* knw   = (const float*)d_in[9];
    const float* knb   = (const float*)d_in[10];
    const float* anw   = (const float*)d_in[11];
    const float* anb   = (const float*)d_in[12];
    const float* fnw   = (const float*)d_in[13];
    const float* fnb   = (const float*)d_in[14];
    const float* w1    = (const float*)d_in[15];
    const float* w2    = (const float*)d_in[16];
    const float* w3    = (const float*)d_in[17];
    const float* rw    = (const float*)d_in[18];
    const float* rb    = (const float*)d_in[19];
    const float* adaw  = (const float*)d_in[20];
    const float* adab  = (const float*)d_in[21];
    float* out = (float*)d_out;

    float *silu_, *ada_, *q_, *k_, *sc_, *x1_, *h2_, *lg_, *pr_, *ebuf_, *tw_;
    bf *hs_, *wqT_, *wkT_, *wvT_, *woT_, *qT_, *kT_, *vs_, *at_, *aos_, *h2s_, *w1T_, *w3T_, *w2T_, *gs_;
    int *cnt_, *list_, *te_, *tp_;
    cudaGetSymbolAddress((void**)&silu_, g_silu);
    cudaGetSymbolAddress((void**)&ada_,  g_ada);
    cudaGetSymbolAddress((void**)&hs_,   g_hs);
    cudaGetSymbolAddress((void**)&wqT_,  g_wqT);
    cudaGetSymbolAddress((void**)&wkT_,  g_wkT);
    cudaGetSymbolAddress((void**)&wvT_,  g_wvT);
    cudaGetSymbolAddress((void**)&woT_,  g_woT);
    cudaGetSymbolAddress((void**)&q_,    g_q);
    cudaGetSymbolAddress((void**)&k_,    g_k);
    cudaGetSymbolAddress((void**)&qT_,   g_qT);
    cudaGetSymbolAddress((void**)&kT_,   g_kT);
    cudaGetSymbolAddress((void**)&vs_,   g_vs);
    cudaGetSymbolAddress((void**)&sc_,   g_sc);
    cudaGetSymbolAddress((void**)&at_,   g_at);
    cudaGetSymbolAddress((void**)&aos_,  g_aos);
    cudaGetSymbolAddress((void**)&x1_,   g_x1);
    cudaGetSymbolAddress((void**)&h2_,   g_h2);
    cudaGetSymbolAddress((void**)&h2s_,  g_h2s);
    cudaGetSymbolAddress((void**)&w1T_,  g_w1T);
    cudaGetSymbolAddress((void**)&w3T_,  g_w3T);
    cudaGetSymbolAddress((void**)&w2T_,  g_w2T);
    cudaGetSymbolAddress((void**)&gs_,   g_gs);
    cudaGetSymbolAddress((void**)&ebuf_, g_ebuf);
    cudaGetSymbolAddress((void**)&lg_,   g_lg);
    cudaGetSymbolAddress((void**)&pr_,   g_pr);
    cudaGetSymbolAddress((void**)&tw_,   g_tw);
    cudaGetSymbolAddress((void**)&cnt_,  g_cnt);
    cudaGetSymbolAddress((void**)&list_, g_list);
    cudaGetSymbolAddress((void**)&te_,   g_te);
    cudaGetSymbolAddress((void**)&tp_,   g_tp);

    cudaFuncSetAttribute(hgemm<0,false>, cudaFuncAttributeMaxDynamicSharedMemorySize, SMEM1);
    cudaFuncSetAttribute(hgemm<1,false>, cudaFuncAttributeMaxDynamicSharedMemorySize, SMEM1);
    cudaFuncSetAttribute(hgemm<2,false>, cudaFuncAttributeMaxDynamicSharedMemorySize, SMEM1);
    cudaFuncSetAttribute(hgemm<0,true>,  cudaFuncAttributeMaxDynamicSharedMemorySize, SMEM1);
    cudaFuncSetAttribute(hgemm2, cudaFuncAttributeMaxDynamicSharedMemorySize, SMEM2);

    const float eps = 1e-5f;

    // 1 silu, 2 ada
    silu_kernel<<<(B_*D_ + 255)/256, 256>>>(adaln, silu_);
    ada_kernel<<<ADA6/128, 128>>>(silu_, adaw, adab, ada_);
    // 3 wq prep, 4 LN(h), 5 q GEMM   <- launch #5 is a main GEMM for ncu
    transS<<<dim3(D_/32, D_/32, 1), 256>>>(wq, wqT_, D_, D_, 0, 0);
    ln_kernel<<<BS_, 256>>>(x, nullptr, hs_, anw, anb, ada_ + D_, ada_, ADA6, eps);
    hgemm<0,false><<<dim3(16,8,1), 256, SMEM1>>>(hs_, 0, wqT_, 0, D_, D_, BS_,
        nullptr, nullptr, q_, 0, nullptr, 0, 0, nullptr, nullptr, 0);
    // k, v
    transS<<<dim3(D_/32, D_/32, 1), 256>>>(wk, wkT_, D_, D_, 0, 0);
    hgemm<0,false><<<dim3(16,8,1), 256, SMEM1>>>(hs_, 0, wkT_, 0, D_, D_, BS_,
        nullptr, nullptr, k_, 0, nullptr, 0, 0, nullptr, nullptr, 0);
    transS<<<dim3(D_/32, D_/32, 1), 256>>>(wv, wvT_, D_, D_, 0, 0);
    hgemm<2,false><<<dim3(16,8,1), 256, SMEM1>>>(hs_, 0, wvT_, 0, D_, D_, BS_,
        nullptr, nullptr, nullptr, 0, vs_, D_, 0, nullptr, nullptr, 0);
    // remaining weight preps
    transS<<<dim3(D_/32, D_/32, 1), 256>>>(wo, woT_, D_, D_, 0, 0);
    transS<<<dim3(H_/32, D_/32, E_), 256>>>(w1, w1T_, D_, H_, (long)D_*H_, (long)H_*K2D);
    transS<<<dim3(H_/32, D_/32, E_), 256>>>(w3, w3T_, D_, H_, (long)D_*H_, (long)H_*K2D);
    transS<<<dim3(D_/32, H_/32, E_), 256>>>(w2, w2T_, H_, D_, (long)H_*D_, (long)D_*K2H);

    // q_norm / k_norm + transpose-split
    ln_kernel<<<BS_, 256>>>(q_, q_, nullptr, qnw, qnb, nullptr, nullptr, 0, eps);
    ln_kernel<<<BS_, 256>>>(k_, k_, nullptr, knw, knb, nullptr, nullptr, 0, eps);
    transS<<<dim3(D_/32, S_/32, B_), 256>>>(q_, qT_, S_, D_, (long)S_*D_, (long)D_*K2D);
    transS<<<dim3(D_/32, S_/32, B_), 256>>>(k_, kT_, S_, D_, (long)S_*D_, (long)D_*K2D);

    // scores[b] = q^T k
    hgemm<0,false><<<dim3(4,8,B_), 256, SMEM1>>>(qT_, (long)D_*K2D, kT_, (long)D_*K2D,
        S_, D_, D_, nullptr, nullptr, sc_, (long)D_*D_, nullptr, 0, 0, nullptr, nullptr, 0);
    softmax_kernel<<<B_*D_, 256>>>(sc_, at_);
    // ao[b] = v @ attn^T
    hgemm<2,false><<<dim3(4,8,B_), 256, SMEM1>>>(vs_, (long)S_*K2D, at_, (long)D_*K2D,
        D_, D_, S_, nullptr, nullptr, nullptr, 0, aos_, D_, (long)S_*K2D, nullptr, nullptr, 0);
    // x1 = x + gate_msa * (ao @ wo)
    hgemm<1,false><<<dim3(16,8,1), 256, SMEM1>>>(aos_, 0, woT_, 0, D_, D_, BS_,
        nullptr, nullptr, x1_, 0, nullptr, 0, 0, x, ada_ + 2L*D_, ADA6);

    // h2 = modulate(LN(x1), mlp)
    ln_kernel<<<BS_, 256>>>(x1_, h2_, h2s_, fnw, fnb, ada_ + 4L*D_, ada_ + 3L*D_, ADA6, eps);

    // router + dispatch (exact fp32)
    router_kernel<<<BS_, 256>>>(h2_, rw, rb, lg_);
    seqnorm_kernel<<<B_*E_, 256>>>(lg_);
    zero_kernel<<<1, 32>>>(cnt_);
    topk_kernel<<<BS_/256, 256>>>(lg_, pr_, cnt_, list_, te_, tp_, tw_);

    // MoE up (fused dual-B): gs = split(sin(h2@w1^T) * (h2@w3^T))
    hgemm2<<<dim3(CAP/128, H_/128, E_), 256, SMEM2>>>(h2s_, w1T_, w3T_, (long)H_*K2D,
        D_, H_, CAP, cnt_, list_, gs_, (long)CAP*K2H);

    // MoE down
    hgemm<0,false><<<dim3(16,8,E_), 256, SMEM1>>>(gs_, (long)CAP*K2H, w2T_, (long)D_*K2H,
        H_, D_, CAP, cnt_, nullptr, ebuf_, (long)CAP*D_, nullptr, 0, 0, nullptr, nullptr, 0);

    // combine + aux
    combine_kernel<<<(int)(BSD/256), 256>>>(ebuf_, te_, tp_, tw_, out);
    aux_kernel<<<1, 256>>>(pr_, out, (long)out_size);
}

// round 6
// speedup vs baseline: 2.7852x; 1.0056x over previous
#include <cuda_runtime.h>
#include <cuda_bf16.h>
#include <math.h>

typedef unsigned int u32;
typedef __nv_bfloat16 bf;

#define B_  4
#define S_  1024
#define D_  1024
#define E_  4
#define H_  2816
#define BS_ (B_*S_)
#define CAP BS_
#define ADA6 (6*D_)
#define BSD ((long)BS_*D_)
#define K2D 2048
#define K2H (2*H_)
#define STG1 49152
#define SMEM1 (4*STG1)
#define SMEM2 (4*STG1)

// ---------------- device scratch ----------------
__device__ __align__(16) float g_silu[B_*D_];
__device__ __align__(16) float g_ada [B_*ADA6];
__device__ __align__(16) bf    g_hs  [(long)BS_*K2D];
__device__ __align__(16) bf    g_wqkvT[(long)3*D_*K2D];
__device__ __align__(16) bf    g_woT [(long)D_*K2D];
__device__ __align__(16) float g_q   [BS_*D_];
__device__ __align__(16) float g_k   [BS_*D_];
__device__ __align__(16) bf    g_qT  [(long)B_*D_*K2D];
__device__ __align__(16) bf    g_kT  [(long)B_*D_*K2D];
__device__ __align__(16) bf    g_vs  [(long)BS_*K2D];
__device__ __align__(16) float g_sc  [(long)B_*D_*D_];
__device__ __align__(16) bf    g_at  [(long)B_*D_*K2D];
__device__ __align__(16) bf    g_aos [(long)BS_*K2D];
__device__ __align__(16) float g_x1  [BS_*D_];
__device__ __align__(16) float g_h2  [BS_*D_];
__device__ __align__(16) bf    g_h2s [(long)BS_*K2D];
__device__ __align__(16) bf    g_w1T [(long)E_*H_*K2D];
__device__ __align__(16) bf    g_w3T [(long)E_*H_*K2D];
__device__ __align__(16) bf    g_w2T [(long)E_*D_*K2H];
__device__ __align__(16) bf    g_gs  [(long)E_*CAP*K2H];
__device__ __align__(16) float g_ebuf[(long)E_*CAP*D_];
__device__ __align__(16) float g_lg  [BS_*E_];
__device__ __align__(16) float g_pr  [BS_*E_];
__device__ int   g_cnt [E_];
__device__ int   g_list[E_*CAP];
__device__ int   g_te  [BS_*2];
__device__ int   g_tp  [BS_*2];
__device__ __align__(16) float g_tw  [BS_*2];

// ---------------- helpers ----------------
__device__ __forceinline__ u32 smem_u32(const void* p) {
    u32 a;
    asm("{ .reg .u64 t; cvta.to.shared.u64 t, %1; cvt.u32.u64 %0, t; }" : "=r"(a) : "l"(p));
    return a;
}
__device__ __forceinline__ u32 swz(u32 o) { return o ^ ((o >> 3) & 0x70); }
__device__ __forceinline__ void bsplit(float v, bf& h, bf& l) {
    h = __float2bfloat16(v);
    l = __float2bfloat16(v - __bfloat162float(h));
}
__device__ __forceinline__ u32 pk2(bf a, bf b) {
    return (u32)__bfloat16_as_ushort(a) | ((u32)__bfloat16_as_ushort(b) << 16);
}
#define CP16(dst, src) asm volatile("cp.async.cg.shared.global [%0], [%1], 16;" :: "r"(dst), "l"(src))
#define CP_COMMIT()    asm volatile("cp.async.commit_group;")
#define CP_WAIT2()     asm volatile("cp.async.wait_group 2;")
#define LDM4(r, ad) asm volatile("ldmatrix.sync.aligned.m8n8.x4.shared.b16 {%0,%1,%2,%3}, [%4];" \
    : "=r"((r)[0]), "=r"((r)[1]), "=r"((r)[2]), "=r"((r)[3]) : "r"(ad))
#define MMA(c, a, b0, b1) asm volatile( \
    "mma.sync.aligned.m16n8k16.row.col.f32.bf16.bf16.f32 " \
    "{%0,%1,%2,%3}, {%4,%5,%6,%7}, {%8,%9}, {%0,%1,%2,%3};" \
    : "+f"((c)[0]), "+f"((c)[1]), "+f"((c)[2]), "+f"((c)[3]) \
    : "r"((a)[0]), "r"((a)[1]), "r"((a)[2]), "r"((a)[3]), "r"(b0), "r"(b1))

// ============ single-B GEMM: C[M,N] = A[M,2K](3seg) * B[N,2K](3seg)^T ============
// 256x128 CTA, 8 warps 64x64, 4-stage cp.async. seg map: A hi,hi,lo  B hi,lo,hi
// EPI 0: fp32  1: resid+gate*acc  2: split [hi|lo] bf16  4: QKV-sectioned (q fp32/k fp32/v split)
template<int EPI, bool GATHER>
__global__ void __launch_bounds__(256, 1) hgemm(
    const bf* __restrict__ A, long aZ,
    const bf* __restrict__ Bm, long bZ,
    int Kr, int N, int Mcap,
    const int* __restrict__ counts, const int* __restrict__ list,
    float* __restrict__ Cf, float* __restrict__ Ck, long cZ,
    bf* __restrict__ Cs, int outW, long csZ,
    const float* __restrict__ aux,
    const float* __restrict__ gate, int gateStride)
{
    extern __shared__ __align__(16) char smem[];
    const int z = blockIdx.z;
    const int Meff = counts ? counts[z] : Mcap;
    const int m0 = blockIdx.x * 256;
    if (m0 >= Meff) return;
    const int n0 = blockIdx.y * 128;
    const int tid = threadIdx.x, wid = tid >> 5, lane = tid & 31;
    const int wm = wid >> 1, wn = wid & 1;
    const u32 sb = smem_u32(smem);
    const long K2 = 2L * Kr;

    const bf* Az = A + (long)z * aZ;
    const bf* Bz = Bm + (long)z * bZ;

    long aRow[8];
    int  jA = tid & 7;
#pragma unroll
    for (int i = 0; i < 8; i++) {
        int r = (i * 256 + tid) >> 3;
        int gm = m0 + r; if (gm > Meff - 1) gm = Meff - 1;
        aRow[i] = GATHER ? (long)list[(long)z * CAP + gm] : (long)gm;
    }
    u32 dA[8], dB[4];
#pragma unroll
    for (int i = 0; i < 8; i++) { int r = (i * 256 + tid) >> 3; dA[i] = swz((u32)(r * 128 + jA * 16)); }
#pragma unroll
    for (int i = 0; i < 4; i++) { int r = (i * 256 + tid) >> 3; dB[i] = swz((u32)(r * 128 + jA * 16)); }

    float acc[4][8][4];
#pragma unroll
    for (int a = 0; a < 4; a++)
#pragma unroll
        for (int b = 0; b < 8; b++)
#pragma unroll
            for (int c = 0; c < 4; c++) acc[a][b][c] = 0.f;

    const int seglen = Kr >> 6;
    const int NC = 3 * seglen;

    auto issue = [&](int c) {
        int seg = c / seglen;
        int kin = (c - seg * seglen) << 6;
        int aOff = (seg == 2 ? Kr : 0) + kin + jA * 8;
        int bOff = (seg == 1 ? Kr : 0) + kin + jA * 8;
        u32 base = sb + (u32)(c & 3) * STG1;
#pragma unroll
        for (int i = 0; i < 8; i++)
            CP16(base + dA[i], Az + aRow[i] * K2 + aOff);
#pragma unroll
        for (int i = 0; i < 4; i++) {
            int r = (i * 256 + tid) >> 3;
            CP16(base + 32768 + dB[i], Bz + (long)(n0 + r) * K2 + bOff);
        }
    };

    issue(0); CP_COMMIT();
    issue(1); CP_COMMIT();
    issue(2); CP_COMMIT();

    for (int c = 0; c < NC; c++) {
        CP_WAIT2();
        __syncthreads();
        if (c + 3 < NC) issue(c + 3);
        CP_COMMIT();
        u32 aB = sb + (u32)(c & 3) * STG1, bB = aB + 32768;
#pragma unroll
        for (int s = 0; s < 4; s++) {
            u32 afr[4][4], bfr[4][4];
#pragma unroll
            for (int mi = 0; mi < 4; mi++) {
                int row = wm * 64 + mi * 16 + (lane & 7) + ((lane >> 3) & 1) * 8;
                int kb = s * 32 + (lane >> 4) * 16;
                LDM4(afr[mi], aB + swz((u32)(row * 128 + kb)));
            }
#pragma unroll
            for (int ni = 0; ni < 4; ni++) {
                int nrow = wn * 64 + ni * 16 + (lane & 7) + (lane >> 4) * 8;
                int kb = s * 32 + ((lane >> 3) & 1) * 16;
                LDM4(bfr[ni], bB + swz((u32)(nrow * 128 + kb)));
            }
#pragma unroll
            for (int mi = 0; mi < 4; mi++)
#pragma unroll
                for (int nj = 0; nj < 8; nj++)
                    MMA(acc[mi][nj], afr[mi], bfr[nj >> 1][(nj & 1) * 2], bfr[nj >> 1][(nj & 1) * 2 + 1]);
        }
    }

#pragma unroll
    for (int mi = 0; mi < 4; mi++) {
#pragma unroll
        for (int half = 0; half < 2; half++) {
            int row = m0 + wm * 64 + mi * 16 + (lane >> 2) + half * 8;
            if (row >= Meff) continue;
#pragma unroll
            for (int nj = 0; nj < 8; nj++) {
                int col = n0 + wn * 64 + nj * 8 + (lane & 3) * 2;
                float v0 = acc[mi][nj][half * 2], v1 = acc[mi][nj][half * 2 + 1];
                if (EPI == 0) {
                    *(float2*)(Cf + (long)z * cZ + (long)row * N + col) = make_float2(v0, v1);
                } else if (EPI == 1) {
                    int bb = row >> 10;
                    const float2 rs = *(const float2*)(aux + (long)row * N + col);
                    const float* gv = gate + (long)bb * gateStride + col;
                    *(float2*)(Cf + (long)row * N + col) = make_float2(rs.x + gv[0] * v0, rs.y + gv[1] * v1);
                } else if (EPI == 4) {
                    if (col < 1024) {
                        *(float2*)(Cf + (long)row * 1024 + col) = make_float2(v0, v1);
                    } else if (col < 2048) {
                        *(float2*)(Ck + (long)row * 1024 + (col - 1024)) = make_float2(v0, v1);
                    } else {
                        int cc = col - 2048;
                        bf h0, l0, h1, l1;
                        bsplit(v0, h0, l0); bsplit(v1, h1, l1);
                        bf* o = Cs + (long)row * 2048 + cc;
                        *(u32*)(o) = pk2(h0, h1);
                        *(u32*)(o + 1024) = pk2(l0, l1);
                    }
                } else {
                    bf h0, l0, h1, l1;
                    bsplit(v0, h0, l0); bsplit(v1, h1, l1);
                    bf* o = Cs + (long)z * csZ + (long)row * 2 * outW + col;
                    *(u32*)(o) = pk2(h0, h1);
                    *(u32*)(o + outW) = pk2(l0, l1);
                }
            }
        }
    }
}

// ============ dual-B GEMM (MoE up, fused): gs = split(sin(A*B1^T) * (A*B2^T)) ============
__global__ void __launch_bounds__(256, 1) hgemm2(
    const bf* __restrict__ A,
    const bf* __restrict__ B1m, const bf* __restrict__ B2m, long bZ,
    int Kr, int N, int Mcap,
    const int* __restrict__ counts, const int* __restrict__ list,
    bf* __restrict__ Cs, long csZ)
{
    extern __shared__ __align__(16) char smem[];
    const int z = blockIdx.z;
    const int Meff = counts[z];
    const int m0 = blockIdx.x * 128;
    if (m0 >= Meff) return;
    const int n0 = blockIdx.y * 128;
    const int tid = threadIdx.x, wid = tid >> 5, lane = tid & 31;
    const int wm = wid >> 2, wn = wid & 3;
    const u32 sb = smem_u32(smem);
    const long K2 = 2L * Kr;

    const bf* B1z = B1m + (long)z * bZ;
    const bf* B2z = B2m + (long)z * bZ;

    long aRow[4];
    int jA = tid & 7;
#pragma unroll
    for (int i = 0; i < 4; i++) {
        int r = (i * 256 + tid) >> 3;
        int gm = m0 + r; if (gm > Meff - 1) gm = Meff - 1;
        aRow[i] = (long)list[(long)z * CAP + gm];
    }
    u32 dT[4];
#pragma unroll
    for (int i = 0; i < 4; i++) { int r = (i * 256 + tid) >> 3; dT[i] = swz((u32)(r * 128 + jA * 16)); }

    float acc1[4][4][4], acc2[4][4][4];
#pragma unroll
    for (int a = 0; a < 4; a++)
#pragma unroll
        for (int b = 0; b < 4; b++)
#pragma unroll
            for (int c = 0; c < 4; c++) { acc1[a][b][c] = 0.f; acc2[a][b][c] = 0.f; }

    const int seglen = Kr >> 6;
    const int NC = 3 * seglen;

    auto issue = [&](int c) {
        int seg = c / seglen;
        int kin = (c - seg * seglen) << 6;
        int aOff = (seg == 2 ? Kr : 0) + kin + jA * 8;
        int bOff = (seg == 1 ? Kr : 0) + kin + jA * 8;
        u32 base = sb + (u32)(c & 3) * STG1;
#pragma unroll
        for (int i = 0; i < 4; i++) {
            int r = (i * 256 + tid) >> 3;
            CP16(base + dT[i], A + aRow[i] * K2 + aOff);
            CP16(base + 16384 + dT[i], B1z + (long)(n0 + r) * K2 + bOff);
            CP16(base + 32768 + dT[i], B2z + (long)(n0 + r) * K2 + bOff);
        }
    };

    issue(0); CP_COMMIT();
    issue(1); CP_COMMIT();
    issue(2); CP_COMMIT();

    for (int c = 0; c < NC; c++) {
        CP_WAIT2();
        __syncthreads();
        if (c + 3 < NC) issue(c + 3);
        CP_COMMIT();
        u32 aB = sb + (u32)(c & 3) * STG1, b1B = aB + 16384, b2B = aB + 32768;
#pragma unroll
        for (int s = 0; s < 4; s++) {
            u32 afr[4][4], bfr1[2][4], bfr2[2][4];
#pragma unroll
            for (int mi = 0; mi < 4; mi++) {
                int row = wm * 64 + mi * 16 + (lane & 7) + ((lane >> 3) & 1) * 8;
                int kb = s * 32 + (lane >> 4) * 16;
                LDM4(afr[mi], aB + swz((u32)(row * 128 + kb)));
            }
#pragma unroll
            for (int bi = 0; bi < 2; bi++) {
                int nrow = wn * 32 + bi * 16 + (lane & 7) + (lane >> 4) * 8;
                int kb = s * 32 + ((lane >> 3) & 1) * 16;
                LDM4(bfr1[bi], b1B + swz((u32)(nrow * 128 + kb)));
                LDM4(bfr2[bi], b2B + swz((u32)(nrow * 128 + kb)));
            }
#pragma unroll
            for (int mi = 0; mi < 4; mi++)
#pragma unroll
                for (int nj = 0; nj < 4; nj++) {
                    MMA(acc1[mi][nj], afr[mi], bfr1[nj >> 1][(nj & 1) * 2], bfr1[nj >> 1][(nj & 1) * 2 + 1]);
                    MMA(acc2[mi][nj], afr[mi], bfr2[nj >> 1][(nj & 1) * 2], bfr2[nj >> 1][(nj & 1) * 2 + 1]);
                }
        }
    }

#pragma unroll
    for (int mi = 0; mi < 4; mi++) {
#pragma unroll
        for (int half = 0; half < 2; half++) {
            int row = m0 + wm * 64 + mi * 16 + (lane >> 2) + half * 8;
            if (row >= Meff) continue;
#pragma unroll
            for (int nj = 0; nj < 4; nj++) {
                int col = n0 + wn * 32 + nj * 8 + (lane & 3) * 2;
                float v0 = sinf(acc1[mi][nj][half * 2]) * acc2[mi][nj][half * 2];
                float v1 = sinf(acc1[mi][nj][half * 2 + 1]) * acc2[mi][nj][half * 2 + 1];
                bf h0, l0, h1, l1;
                bsplit(v0, h0, l0); bsplit(v1, h1, l1);
                bf* o = Cs + (long)z * csZ + (long)row * (long)(2 * N) + col;
                *(u32*)(o) = pk2(h0, h1);
                *(u32*)(o + N) = pk2(l0, l1);
            }
        }
    }
}

// ---------------- prep kernels ----------------
// transpose + split: fp32 [R,C] -> bf16 [C, 2R] planes [hi|lo]; 64x64 tiles
__global__ void __launch_bounds__(256) transS(const float* __restrict__ in, bf* __restrict__ out,
                                              int R, int C, long inZ, long outZ)
{
    __shared__ float t[64][65];
    int z = blockIdx.z;
    const float* iz = in + (long)z * inZ;
    bf* oz = out + (long)z * outZ;
    int c0 = blockIdx.x * 64, r0 = blockIdx.y * 64;
    int tid = threadIdx.x;
    int lc = (tid & 15) * 4, lr = tid >> 4;
#pragma unroll
    for (int p = 0; p < 4; p++) {
        int r = lr + p * 16;
        float4 v = *(const float4*)&iz[(long)(r0 + r) * C + c0 + lc];
        t[r][lc] = v.x; t[r][lc + 1] = v.y; t[r][lc + 2] = v.z; t[r][lc + 3] = v.w;
    }
    __syncthreads();
    int wr = (tid & 15) * 4, wc = tid >> 4;
#pragma unroll
    for (int p = 0; p < 4; p++) {
        int c = wc + p * 16;
        float v0 = t[wr + 0][c], v1 = t[wr + 1][c], v2 = t[wr + 2][c], v3 = t[wr + 3][c];
        bf h0, l0, h1, l1, h2, l2, h3, l3;
        bsplit(v0, h0, l0); bsplit(v1, h1, l1); bsplit(v2, h2, l2); bsplit(v3, h3, l3);
        long base = (long)(c0 + c) * 2 * R + r0 + wr;
        uint2 hh, ll;
        hh.x = pk2(h0, h1); hh.y = pk2(h2, h3);
        ll.x = pk2(l0, l1); ll.y = pk2(l2, l3);
        *(uint2*)&oz[base] = hh;
        *(uint2*)&oz[base + R] = ll;
    }
}

__global__ void silu_kernel(const float* __restrict__ in, float* __restrict__ o) {
    int i = blockIdx.x * 256 + threadIdx.x;
    if (i < B_ * D_) { float v = in[i]; o[i] = v / (1.f + expf(-v)); }
}

__global__ void __launch_bounds__(128) ada_kernel(const float* __restrict__ sl,
    const float* __restrict__ W, const float* __restrict__ bias, float* __restrict__ ada)
{
    __shared__ float s[B_ * D_];
    int col = blockIdx.x * 128 + threadIdx.x;
    for (int i = threadIdx.x; i < B_ * D_; i += 128) s[i] = sl[i];
    __syncthreads();
    float a0 = 0.f, a1 = 0.f, a2 = 0.f, a3 = 0.f;
    for (int k = 0; k < D_; k++) {
        float w = W[(long)k * ADA6 + col];
        a0 = fmaf(s[k], w, a0); a1 = fmaf(s[D_ + k], w, a1);
        a2 = fmaf(s[2 * D_ + k], w, a2); a3 = fmaf(s[3 * D_ + k], w, a3);
    }
    float bv = bias[col];
    ada[col] = a0 + bv; ada[ADA6 + col] = a1 + bv;
    ada[2L * ADA6 + col] = a2 + bv; ada[3L * ADA6 + col] = a3 + bv;
}

// LN width 1024: warp-per-row, shuffle-only reduction
__global__ void __launch_bounds__(256) ln_kernel(const float* __restrict__ in,
    float* __restrict__ outF, bf* __restrict__ outS,
    const float* __restrict__ w, const float* __restrict__ b,
    const float* __restrict__ scale, const float* __restrict__ shift,
    int adaStride, float eps)
{
    int row = blockIdx.x * 8 + (threadIdx.x >> 5);
    int lane = threadIdx.x & 31;
    const float* xr = in + (long)row * D_;
    float4 v[8];
    float s1 = 0.f, s2 = 0.f;
#pragma unroll
    for (int j = 0; j < 8; j++) {
        v[j] = *(const float4*)&xr[j * 128 + lane * 4];
        s1 += v[j].x + v[j].y + v[j].z + v[j].w;
        s2 += v[j].x * v[j].x + v[j].y * v[j].y + v[j].z * v[j].z + v[j].w * v[j].w;
    }
#pragma unroll
    for (int o = 16; o; o >>= 1) {
        s1 += __shfl_xor_sync(0xffffffffu, s1, o);
        s2 += __shfl_xor_sync(0xffffffffu, s2, o);
    }
    float mean = s1 * (1.f / D_);
    float var = s2 * (1.f / D_) - mean * mean;
    float rs = rsqrtf(var + eps);
    int bb = row >> 10;
#pragma unroll
    for (int j = 0; j < 8; j++) {
        int c0 = j * 128 + lane * 4;
        float4 wv = *(const float4*)&w[c0];
        float4 bv = *(const float4*)&b[c0];
        float o4[4];
        o4[0] = (v[j].x - mean) * rs * wv.x + bv.x;
        o4[1] = (v[j].y - mean) * rs * wv.y + bv.y;
        o4[2] = (v[j].z - mean) * rs * wv.z + bv.z;
        o4[3] = (v[j].w - mean) * rs * wv.w + bv.w;
        if (scale) {
            float4 sv = *(const float4*)&scale[(long)bb * adaStride + c0];
            float4 hv = *(const float4*)&shift[(long)bb * adaStride + c0];
            o4[0] = o4[0] * (1.f + sv.x) + hv.x;
            o4[1] = o4[1] * (1.f + sv.y) + hv.y;
            o4[2] = o4[2] * (1.f + sv.z) + hv.z;
            o4[3] = o4[3] * (1.f + sv.w) + hv.w;
        }
        if (outF)
            *(float4*)&outF[(long)row * D_ + c0] = make_float4(o4[0], o4[1], o4[2], o4[3]);
        if (outS) {
            bf h0, l0, h1, l1, h2, l2, h3, l3;
            bsplit(o4[0], h0, l0); bsplit(o4[1], h1, l1);
            bsplit(o4[2], h2, l2); bsplit(o4[3], h3, l3);
            bf* os = outS + (long)row * K2D;
            uint2 hh, ll;
            hh.x = pk2(h0, h1); hh.y = pk2(h2, h3);
            ll.x = pk2(l0, l1); ll.y = pk2(l2, l3);
            *(uint2*)&os[c0] = hh;
            *(uint2*)&os[D_ + c0] = ll;
        }
    }
}

// softmax width 1024: warp-per-row, split [hi|lo] output
__global__ void __launch_bounds__(256) softmax_kernel(const float* __restrict__ p, bf* __restrict__ outS) {
    int row = blockIdx.x * 8 + (threadIdx.x >> 5);
    int lane = threadIdx.x & 31;
    const float* r = p + (long)row * D_;
    float4 v[8];
    float m = -1e30f;
#pragma unroll
    for (int j = 0; j < 8; j++) {
        v[j] = *(const float4*)&r[j * 128 + lane * 4];
        m = fmaxf(m, fmaxf(fmaxf(v[j].x, v[j].y), fmaxf(v[j].z, v[j].w)));
    }
#pragma unroll
    for (int o = 16; o; o >>= 1) m = fmaxf(m, __shfl_xor_sync(0xffffffffu, m, o));
    float s = 0.f;
#pragma unroll
    for (int j = 0; j < 8; j++) {
        v[j].x = expf(v[j].x - m); v[j].y = expf(v[j].y - m);
        v[j].z = expf(v[j].z - m); v[j].w = expf(v[j].w - m);
        s += v[j].x + v[j].y + v[j].z + v[j].w;
    }
#pragma unroll
    for (int o = 16; o; o >>= 1) s += __shfl_xor_sync(0xffffffffu, s, o);
    float inv = 1.f / s;
    bf* os = outS + (long)row * K2D;
#pragma unroll
    for (int j = 0; j < 8; j++) {
        int c0 = j * 128 + lane * 4;
        bf h0, l0, h1, l1, h2, l2, h3, l3;
        bsplit(v[j].x * inv, h0, l0); bsplit(v[j].y * inv, h1, l1);
        bsplit(v[j].z * inv, h2, l2); bsplit(v[j].w * inv, h3, l3);
        uint2 hh, ll;
        hh.x = pk2(h0, h1); hh.y = pk2(h2, h3);
        ll.x = pk2(l0, l1); ll.y = pk2(l2, l3);
        *(uint2*)&os[c0] = hh;
        *(uint2*)&os[D_ + c0] = ll;
    }
}

__global__ void __launch_bounds__(256) router_kernel(const float* __restrict__ h,
    const float* __restrict__ rw, const float* __restrict__ rb, float* __restrict__ lg)
{
    int tok = blockIdx.x * 8 + (threadIdx.x >> 5);
    int lane = threadIdx.x & 31;
    const float* hr = h + (long)tok * D_;
    float a0 = 0.f, a1 = 0.f, a2 = 0.f, a3 = 0.f;
#pragma unroll
    for (int j = 0; j < 8; j++) {
        float4 hv = *(const float4*)&hr[j * 128 + lane * 4];
        float hvv[4] = { hv.x, hv.y, hv.z, hv.w };
#pragma unroll
        for (int u = 0; u < 4; u++) {
            int k = j * 128 + lane * 4 + u;
            float4 wv = *(const float4*)&rw[(long)k * 4];
            a0 = fmaf(hvv[u], wv.x, a0); a1 = fmaf(hvv[u], wv.y, a1);
            a2 = fmaf(hvv[u], wv.z, a2); a3 = fmaf(hvv[u], wv.w, a3);
        }
    }
#pragma unroll
    for (int o = 16; o; o >>= 1) {
        a0 += __shfl_xor_sync(0xffffffffu, a0, o);
        a1 += __shfl_xor_sync(0xffffffffu, a1, o);
        a2 += __shfl_xor_sync(0xffffffffu, a2, o);
        a3 += __shfl_xor_sync(0xffffffffu, a3, o);
    }
    if (lane == 0) {
        lg[(long)tok * 4 + 0] = a0 + rb[0];
        lg[(long)tok * 4 + 1] = a1 + rb[1];
        lg[(long)tok * 4 + 2] = a2 + rb[2];
        lg[(long)tok * 4 + 3] = a3 + rb[3];
    }
}

__global__ void __launch_bounds__(256) seqnorm_kernel(float* __restrict__ lg) {
    int b = blockIdx.x >> 2, e = blockIdx.x & 3;
    int t = threadIdx.x;
    float s = 0.f;
    for (int i = t; i < S_; i += 256) {
        float v = lg[((long)(b * S_ + i)) * 4 + e];
        s += v * v;
    }
    __shared__ float sm[8];
#pragma unroll
    for (int o = 16; o; o >>= 1) s += __shfl_down_sync(0xffffffffu, s, o);
    if ((t & 31) == 0) sm[t >> 5] = s;
    __syncthreads();
    if (t == 0) {
        float a = 0.f;
        for (int i = 0; i < 8; i++) a += sm[i];
        sm[0] = 1.f / fmaxf(sqrtf(a), 1e-12f);
    }
    __syncthreads();
    float sc = sm[0];
    for (int i = t; i < S_; i += 256) lg[((long)(b * S_ + i)) * 4 + e] *= sc;
}

__global__ void zero_kernel(int* cnt) { if (threadIdx.x < E_) cnt[threadIdx.x] = 0; }

__global__ void topk_kernel(const float* __restrict__ lg, float* __restrict__ pr,
    int* __restrict__ cnt, int* __restrict__ list,
    int* __restrict__ te, int* __restrict__ tp, float* __restrict__ tw)
{
    int tok = blockIdx.x * 256 + threadIdx.x;
    if (tok >= BS_) return;
    float l[4];
#pragma unroll
    for (int e = 0; e < 4; e++) l[e] = lg[(long)tok * 4 + e];
    float m = fmaxf(fmaxf(l[0], l[1]), fmaxf(l[2], l[3]));
    float p[4]; float s = 0.f;
#pragma unroll
    for (int e = 0; e < 4; e++) { p[e] = expf(l[e] - m); s += p[e]; }
    float inv = 1.f / s;
#pragma unroll
    for (int e = 0; e < 4; e++) { p[e] *= inv; pr[(long)tok * 4 + e] = p[e]; }
    int a0 = 0;
#pragma unroll
    for (int e = 1; e < 4; e++) if (p[e] > p[a0]) a0 = e;
    int a1 = -1; float pb = -1.f;
#pragma unroll
    for (int e = 0; e < 4; e++) if (e != a0 && p[e] > pb) { pb = p[e]; a1 = e; }
    int s0 = atomicAdd(&cnt[a0], 1); list[a0 * CAP + s0] = tok;
    int s1 = atomicAdd(&cnt[a1], 1); list[a1 * CAP + s1] = tok;
    te[2 * tok] = a0;     tp[2 * tok] = s0;     tw[2 * tok] = p[a0];
    te[2 * tok + 1] = a1; tp[2 * tok + 1] = s1; tw[2 * tok + 1] = p[a1];
}

__global__ void combine_kernel(const float* __restrict__ ebuf,
    const int* __restrict__ te, const int* __restrict__ tp,
    const float* __restrict__ tw, float* __restrict__ out)
{
    long gid = (long)blockIdx.x * 256 + threadIdx.x;
    int tok = (int)(gid >> 10);
    int d = (int)(gid & 1023);
    int e0 = te[2 * tok], e1 = te[2 * tok + 1];
    long r0 = ((long)e0 * CAP + tp[2 * tok]) * D_ + d;
    long r1 = ((long)e1 * CAP + tp[2 * tok + 1]) * D_ + d;
    out[gid] = tw[2 * tok] * ebuf[r0] + tw[2 * tok + 1] * ebuf[r1];
}

__global__ void __launch_bounds__(256) aux_kernel(const float* __restrict__ pr,
                                                  float* __restrict__ out, long out_size)
{
    int t = threadIdx.x;
    float acc = 0.f;
    for (int i = t; i < S_ * E_; i += 256) {
        int s = i >> 2, e = i & 3;
        float av = 0.f;
#pragma unroll
        for (int b = 0; b < B_; b++) av += pr[((long)(b * S_ + s)) * 4 + e];
        av *= 0.25f;
        float d = 0.25f - av;
        acc += d * d;
    }
    __shared__ float sm[8];
#pragma unroll
    for (int o = 16; o; o >>= 1) acc += __shfl_down_sync(0xffffffffu, acc, o);
    if ((t & 31) == 0) sm[t >> 5] = acc;
    __syncthreads();
    if (t == 0) {
        float a = 0.f;
        for (int i = 0; i < 8; i++) a += sm[i];
        for (long i = BSD; i < out_size; i++) out[i] = a;
    }
}

// ---------------- host launcher ----------------
extern "C" void kernel_launch(void* const* d_in, const int* in_sizes, int n_in,
                              void* d_out, int out_size)
{
    (void)in_sizes; (void)n_in;
    const float* x     = (const float*)d_in[0];
    const float* adaln = (const float*)d_in[2];
    const float* wq    = (const float*)d_in[3];
    const float* wk    = (const float*)d_in[4];
    const float* wv    = (const float*)d_in[5];
    const float* wo    = (const float*)d_in[6];
    const float* qnw   = (const float*)d_in[7];
    const float* qnb   = (const float*)d_in[8];
    const float* knw   = (const float*)d_in[9];
    const float* knb   = (const float*)d_in[10];
    const float* anw   = (const float*)d_in[11];
    const float* anb   = (const float*)d_in[12];
    const float* fnw   = (const float*)d_in[13];
    const float* fnb   = (const float*)d_in[14];
    const float* w1    = (const float*)d_in[15];
    const float* w2    = (const float*)d_in[16];
    const float* w3    = (const float*)d_in[17];
    const float* rw    = (const float*)d_in[18];
    const float* rb    = (const float*)d_in[19];
    const float* adaw  = (const float*)d_in[20];
    const float* adab  = (const float*)d_in[21];
    float* out = (float*)d_out;

    float *silu_, *ada_, *q_, *k_, *sc_, *x1_, *h2_, *lg_, *pr_, *ebuf_, *tw_;
    bf *hs_, *wqkvT_, *woT_, *qT_, *kT_, *vs_, *at_, *aos_, *h2s_, *w1T_, *w3T_, *w2T_, *gs_;
    int *cnt_, *list_, *te_, *tp_;
    cudaGetSymbolAddress((void**)&silu_, g_silu);
    cudaGetSymbolAddress((void**)&ada_,  g_ada);
    cudaGetSymbolAddress((void**)&hs_,   g_hs);
    cudaGetSymbolAddress((void**)&wqkvT_,g_wqkvT);
    cudaGetSymbolAddress((void**)&woT_,  g_woT);
    cudaGetSymbolAddress((void**)&q_,    g_q);
    cudaGetSymbolAddress((void**)&k_,    g_k);
    cudaGetSymbolAddress((void**)&qT_,   g_qT);
    cudaGetSymbolAddress((void**)&kT_,   g_kT);
    cudaGetSymbolAddress((void**)&vs_,   g_vs);
    cudaGetSymbolAddress((void**)&sc_,   g_sc);
    cudaGetSymbolAddress((void**)&at_,   g_at);
    cudaGetSymbolAddress((void**)&aos_,  g_aos);
    cudaGetSymbolAddress((void**)&x1_,   g_x1);
    cudaGetSymbolAddress((void**)&h2_,   g_h2);
    cudaGetSymbolAddress((void**)&h2s_,  g_h2s);
    cudaGetSymbolAddress((void**)&w1T_,  g_w1T);
    cudaGetSymbolAddress((void**)&w3T_,  g_w3T);
    cudaGetSymbolAddress((void**)&w2T_,  g_w2T);
    cudaGetSymbolAddress((void**)&gs_,   g_gs);
    cudaGetSymbolAddress((void**)&ebuf_, g_ebuf);
    cudaGetSymbolAddress((void**)&lg_,   g_lg);
    cudaGetSymbolAddress((void**)&pr_,   g_pr);
    cudaGetSymbolAddress((void**)&tw_,   g_tw);
    cudaGetSymbolAddress((void**)&cnt_,  g_cnt);
    cudaGetSymbolAddress((void**)&list_, g_list);
    cudaGetSymbolAddress((void**)&te_,   g_te);
    cudaGetSymbolAddress((void**)&tp_,   g_tp);

    cudaFuncSetAttribute(hgemm<0,false>, cudaFuncAttributeMaxDynamicSharedMemorySize, SMEM1);
    cudaFuncSetAttribute(hgemm<1,false>, cudaFuncAttributeMaxDynamicSharedMemorySize, SMEM1);
    cudaFuncSetAttribute(hgemm<2,false>, cudaFuncAttributeMaxDynamicSharedMemorySize, SMEM1);
    cudaFuncSetAttribute(hgemm<4,false>, cudaFuncAttributeMaxDynamicSharedMemorySize, SMEM1);
    cudaFuncSetAttribute(hgemm2, cudaFuncAttributeMaxDynamicSharedMemorySize, SMEM2);

    const float eps = 1e-5f;

    // adaLN + weight prep for QKV (packed) + h
    silu_kernel<<<(B_*D_ + 255)/256, 256>>>(adaln, silu_);
    ada_kernel<<<ADA6/128, 128>>>(silu_, adaw, adab, ada_);
    transS<<<dim3(D_/64, D_/64, 1), 256>>>(wq, wqkvT_, D_, D_, 0, 0);
    transS<<<dim3(D_/64, D_/64, 1), 256>>>(wk, wqkvT_ + (long)D_*K2D, D_, D_, 0, 0);
    transS<<<dim3(D_/64, D_/64, 1), 256>>>(wv, wqkvT_ + 2L*D_*K2D, D_, D_, 0, 0);
    ln_kernel<<<BS_/8, 256>>>(x, nullptr, hs_, anw, anb, ada_ + D_, ada_, ADA6, eps);

    // fused QKV GEMM: q fp32 / k fp32 / v split
    hgemm<4,false><<<dim3(16,24,1), 256, SMEM1>>>(hs_, 0, wqkvT_, 0, D_, 3*D_, BS_,
        nullptr, nullptr, q_, k_, 0, vs_, 1024, 0, nullptr, nullptr, 0);

    // remaining weight preps
    transS<<<dim3(D_/64, D_/64, 1), 256>>>(wo, woT_, D_, D_, 0, 0);
    transS<<<dim3(H_/64, D_/64, E_), 256>>>(w1, w1T_, D_, H_, (long)D_*H_, (long)H_*K2D);
    transS<<<dim3(H_/64, D_/64, E_), 256>>>(w3, w3T_, D_, H_, (long)D_*H_, (long)H_*K2D);
    transS<<<dim3(D_/64, H_/64, E_), 256>>>(w2, w2T_, H_, D_, (long)H_*D_, (long)D_*K2H);

    // q_norm / k_norm + transpose-split
    ln_kernel<<<BS_/8, 256>>>(q_, q_, nullptr, qnw, qnb, nullptr, nullptr, 0, eps);
    ln_kernel<<<BS_/8, 256>>>(k_, k_, nullptr, knw, knb, nullptr, nullptr, 0, eps);
    transS<<<dim3(D_/64, S_/64, B_), 256>>>(q_, qT_, S_, D_, (long)S_*D_, (long)D_*K2D);
    transS<<<dim3(D_/64, S_/64, B_), 256>>>(k_, kT_, S_, D_, (long)S_*D_, (long)D_*K2D);

    // scores[b] = q^T k (A uses hi,hi,lo planes; qT holds [hi|lo] -> same as others via seg map? NO:
    // A seg map needs planes hi,hi,lo; [hi|lo] layout + A offsets (0,0,Kr) gives exactly that.)
    hgemm<0,false><<<dim3(4,8,B_), 256, SMEM1>>>(qT_, (long)D_*K2D, kT_, (long)D_*K2D,
        S_, D_, D_, nullptr, nullptr, sc_, nullptr, (long)D_*D_, nullptr, 0, 0, nullptr, nullptr, 0);
    softmax_kernel<<<B_*D_/8, 256>>>(sc_, at_);
    hgemm<2,false><<<dim3(4,8,B_), 256, SMEM1>>>(vs_, (long)S_*K2D, at_, (long)D_*K2D,
        D_, D_, S_, nullptr, nullptr, nullptr, nullptr, 0, aos_, D_, (long)S_*K2D, nullptr, nullptr, 0);
    hgemm<1,false><<<dim3(16,8,1), 256, SMEM1>>>(aos_, 0, woT_, 0, D_, D_, BS_,
        nullptr, nullptr, x1_, nullptr, 0, nullptr, 0, 0, x, ada_ + 2L*D_, ADA6);

    // h2 = modulate(LN(x1), mlp)
    ln_kernel<<<BS_/8, 256>>>(x1_, h2_, h2s_, fnw, fnb, ada_ + 4L*D_, ada_ + 3L*D_, ADA6, eps);

    // router + dispatch (exact fp32)
    router_kernel<<<BS_/8, 256>>>(h2_, rw, rb, lg_);
    seqnorm_kernel<<<B_*E_, 256>>>(lg_);
    zero_kernel<<<1, 32>>>(cnt_);
    topk_kernel<<<BS_/256, 256>>>(lg_, pr_, cnt_, list_, te_, tp_, tw_);

    // MoE up (fused dual-B) + down
    hgemm2<<<dim3(CAP/128, H_/128, E_), 256, SMEM2>>>(h2s_, w1T_, w3T_, (long)H_*K2D,
        D_, H_, CAP, cnt_, list_, gs_, (long)CAP*K2H);
    hgemm<0,false><<<dim3(16,8,E_), 256, SMEM1>>>(gs_, (long)CAP*K2H, w2T_, (long)D_*K2H,
        H_, D_, CAP, cnt_, nullptr, ebuf_, nullptr, (long)CAP*D_, nullptr, 0, 0, nullptr, nullptr, 0);

    // combine + aux
    combine_kernel<<<(int)(BSD/256), 256>>>(ebuf_, te_, tp_, tw_, out);
    aux_kernel<<<1, 256>>>(pr_, out, (long)out_size);
}